// round 1
// baseline (speedup 1.0000x reference)
#include <cuda_runtime.h>
#include <math.h>

#define Bdim 4
#define Sdim 2048
#define Mdim 2048
#define Hdim 16
#define Ddim 128
#define Rrows (Bdim * Sdim)          // 8192
#define N_QKV (3 * Hdim * Ddim)      // 6144

// Scratch (allocation-free rule: __device__ globals)
__device__ float g_qkv[(size_t)Rrows * N_QKV];   // ~201 MB
__device__ float g_ctx[(size_t)Rrows * Mdim];    // ~67 MB

// ---------------------------------------------------------------------------
// Generic fp32 SGEMM: C[gridDim.y*128, Nc] = A[.,K] @ B[K, Nc], all row-major.
// 128x128 tile, BK=16, 256 threads, 8x8 per thread.
// ---------------------------------------------------------------------------
#define GBM 128
#define GBN 128
#define GBK 16

__global__ __launch_bounds__(256, 2)
void sgemm(const float* __restrict__ A, const float* __restrict__ B,
           float* __restrict__ C, int Nc, int K) {
    __shared__ float sA[GBK][GBM];   // A stored transposed: sA[k][row]
    __shared__ float sB[GBK][GBN];

    const int tid  = threadIdx.x;
    const int tr   = tid >> 4;
    const int tc   = tid & 15;
    const int row0 = tr * 8;
    const int col0 = tc * 8;

    const float* Ab = A + (size_t)blockIdx.y * GBM * K;
    const float* Bb = B + (size_t)blockIdx.x * GBN;

    float acc[8][8];
#pragma unroll
    for (int i = 0; i < 8; i++)
#pragma unroll
        for (int j = 0; j < 8; j++) acc[i][j] = 0.f;

    for (int k0 = 0; k0 < K; k0 += GBK) {
#pragma unroll
        for (int i = 0; i < 2; i++) {
            int f  = i * 256 + tid;
            int r  = f >> 2;
            int c4 = (f & 3) << 2;
            float4 v = *(const float4*)(Ab + (size_t)r * K + k0 + c4);
            sA[c4 + 0][r] = v.x;
            sA[c4 + 1][r] = v.y;
            sA[c4 + 2][r] = v.z;
            sA[c4 + 3][r] = v.w;
        }
#pragma unroll
        for (int i = 0; i < 2; i++) {
            int f  = i * 256 + tid;
            int r  = f >> 5;
            int c4 = (f & 31) << 2;
            *(float4*)(&sB[r][c4]) = *(const float4*)(Bb + (size_t)(k0 + r) * Nc + c4);
        }
        __syncthreads();

#pragma unroll
        for (int kk = 0; kk < GBK; kk++) {
            float a[8], bv[8];
            *(float4*)(a)      = *(const float4*)(&sA[kk][row0]);
            *(float4*)(a + 4)  = *(const float4*)(&sA[kk][row0 + 4]);
            *(float4*)(bv)     = *(const float4*)(&sB[kk][col0]);
            *(float4*)(bv + 4) = *(const float4*)(&sB[kk][col0 + 4]);
#pragma unroll
            for (int i = 0; i < 8; i++)
#pragma unroll
                for (int j = 0; j < 8; j++)
                    acc[i][j] = fmaf(a[i], bv[j], acc[i][j]);
        }
        __syncthreads();
    }

    float* Cb = C + ((size_t)blockIdx.y * GBM + row0) * Nc + (size_t)blockIdx.x * GBN + col0;
#pragma unroll
    for (int i = 0; i < 8; i++) {
        float4 w0 = make_float4(acc[i][0], acc[i][1], acc[i][2], acc[i][3]);
        float4 w1 = make_float4(acc[i][4], acc[i][5], acc[i][6], acc[i][7]);
        *(float4*)(Cb + (size_t)i * Nc)     = w0;
        *(float4*)(Cb + (size_t)i * Nc + 4) = w1;
    }
}

// ---------------------------------------------------------------------------
// RoPE (consecutive-pair variant) applied in-place to q and k inside g_qkv.
// One thread per (row, head, pair). Theta/sincos in double: cheap, and keeps
// our error at/below the reference's own fp32 rounding of the timescales.
// ---------------------------------------------------------------------------
__global__ void rope_kernel(float* __restrict__ qkv) {
    unsigned idx = blockIdx.x * blockDim.x + threadIdx.x;  // < 2^23
    int pair = idx & 63;
    int h    = (idx >> 6) & 15;
    unsigned r = idx >> 10;             // 0..8191
    int s = (int)(r & (Sdim - 1));      // position within sequence

    double frac  = (double)(2 * pair) / (double)Ddim;
    double theta = (double)s * exp(-frac * 9.210340371976184);  // ln(10000)
    double sd, cd;
    sincos(theta, &sd, &cd);
    float sn = (float)sd, cs = (float)cd;

    size_t base = (size_t)r * N_QKV + (size_t)h * Ddim + 2 * pair;

    float2 q = *(float2*)(qkv + base);
    float2 qo;
    qo.x = fmaf(q.x, cs, -q.y * sn);   // even: x*cos - x_next*sin
    qo.y = fmaf(q.y, cs,  q.x * sn);   // odd:  x*cos + x_prev*sin
    *(float2*)(qkv + base) = qo;

    size_t kb = base + 2048;           // k block offset within 6144-wide row
    float2 k = *(float2*)(qkv + kb);
    float2 ko;
    ko.x = fmaf(k.x, cs, -k.y * sn);
    ko.y = fmaf(k.y, cs,  k.x * sn);
    *(float2*)(qkv + kb) = ko;
}

// ---------------------------------------------------------------------------
// Flash attention, fp32 SIMT. 64 q-rows x 64 k-cols per iteration, D=128.
// 256 threads: (ty 0..15, tx 0..15). S phase: 4x4 per thread. PV: 4 rows x 8 cols.
// Online softmax with per-row stats kept in registers (replicated across the
// 16-thread row group; reduced with shfl_xor within the 16-lane half-warp).
// ---------------------------------------------------------------------------
#define FLASH_SMEM_FLOATS (128 * 64 + 128 * 64 + 64 * 128 + 64 * 64)
#define FLASH_SMEM_BYTES  (FLASH_SMEM_FLOATS * 4)

__global__ __launch_bounds__(256)
void flash_attn(const float* __restrict__ qkv, float* __restrict__ ctx) {
    const int qtile = blockIdx.x;
    const int b     = blockIdx.y >> 4;
    const int h     = blockIdx.y & 15;

    extern __shared__ float sm[];
    float* sQt = sm;              // [128][64]  (d-major, transposed)
    float* sKt = sm + 8192;       // [128][64]
    float* sV  = sm + 16384;      // [64][128]
    float* sP  = sm + 24576;      // [64][64]

    const int tid = threadIdx.x;
    const int ty  = tid >> 4;
    const int tx  = tid & 15;

    const size_t rowbase = (size_t)(b * Sdim);
    const size_t qbase   = (rowbase + (size_t)qtile * 64) * N_QKV + (size_t)h * Ddim;

    // Load Q tile transposed into smem (coalesced 64B gmem segments; 4-way STS)
#pragma unroll
    for (int i = 0; i < 8; i++) {
        int f   = i * 256 + tid;
        int lo  = f & 3;
        int mid = (f >> 2) & 63;
        int hi  = f >> 8;
        int row = mid;
        int dc  = hi * 16 + lo * 4;
        float4 v = *(const float4*)(qkv + qbase + (size_t)row * N_QKV + dc);
        sQt[(dc + 0) * 64 + row] = v.x;
        sQt[(dc + 1) * 64 + row] = v.y;
        sQt[(dc + 2) * 64 + row] = v.z;
        sQt[(dc + 3) * 64 + row] = v.w;
    }

    float m_r[4], l_r[4], o[4][8];
#pragma unroll
    for (int i = 0; i < 4; i++) { m_r[i] = -1e30f; l_r[i] = 0.f; }
#pragma unroll
    for (int i = 0; i < 4; i++)
#pragma unroll
        for (int j = 0; j < 8; j++) o[i][j] = 0.f;

    const float scale = 0.08838834764831845f;  // 1/sqrt(128)

    for (int kt = 0; kt <= qtile; kt++) {
        __syncthreads();  // previous PV / Q-store visibility before overwrite

        const size_t kb = (rowbase + (size_t)kt * 64) * N_QKV + (size_t)h * Ddim + 2048;
        const size_t vb = kb + 2048;

        // K tile transposed
#pragma unroll
        for (int i = 0; i < 8; i++) {
            int f   = i * 256 + tid;
            int lo  = f & 3;
            int mid = (f >> 2) & 63;
            int hi  = f >> 8;
            int row = mid;
            int dc  = hi * 16 + lo * 4;
            float4 v = *(const float4*)(qkv + kb + (size_t)row * N_QKV + dc);
            sKt[(dc + 0) * 64 + row] = v.x;
            sKt[(dc + 1) * 64 + row] = v.y;
            sKt[(dc + 2) * 64 + row] = v.z;
            sKt[(dc + 3) * 64 + row] = v.w;
        }
        // V tile (row-major)
#pragma unroll
        for (int i = 0; i < 8; i++) {
            int f   = i * 256 + tid;
            int row = f >> 5;
            int c4  = (f & 31) << 2;
            *(float4*)(sV + row * 128 + c4) =
                *(const float4*)(qkv + vb + (size_t)row * N_QKV + c4);
        }
        __syncthreads();

        // S = (Q K^T) * scale  (4x4 per thread)
        float s4[4][4];
#pragma unroll
        for (int i = 0; i < 4; i++)
#pragma unroll
            for (int j = 0; j < 4; j++) s4[i][j] = 0.f;

#pragma unroll 8
        for (int kk = 0; kk < 128; kk++) {
            float4 a  = *(const float4*)(sQt + kk * 64 + ty * 4);
            float4 bk = *(const float4*)(sKt + kk * 64 + tx * 4);
            float av[4] = {a.x, a.y, a.z, a.w};
            float bv[4] = {bk.x, bk.y, bk.z, bk.w};
#pragma unroll
            for (int i = 0; i < 4; i++)
#pragma unroll
                for (int j = 0; j < 4; j++)
                    s4[i][j] = fmaf(av[i], bv[j], s4[i][j]);
        }

        const bool diag = (kt == qtile);
#pragma unroll
        for (int i = 0; i < 4; i++) {
            int qi = ty * 4 + i;
#pragma unroll
            for (int j = 0; j < 4; j++) {
                int kj = tx * 4 + j;
                if (diag && kj > qi) s4[i][j] = -1e30f;
                else                 s4[i][j] *= scale;
            }
        }

        // Online softmax, row stats reduced across the 16-lane tx group
#pragma unroll
        for (int i = 0; i < 4; i++) {
            float mx = fmaxf(fmaxf(s4[i][0], s4[i][1]), fmaxf(s4[i][2], s4[i][3]));
            mx = fmaxf(mx, __shfl_xor_sync(0xffffffffu, mx, 1));
            mx = fmaxf(mx, __shfl_xor_sync(0xffffffffu, mx, 2));
            mx = fmaxf(mx, __shfl_xor_sync(0xffffffffu, mx, 4));
            mx = fmaxf(mx, __shfl_xor_sync(0xffffffffu, mx, 8));
            float m_new = fmaxf(m_r[i], mx);

            float p0 = __expf(s4[i][0] - m_new);
            float p1 = __expf(s4[i][1] - m_new);
            float p2 = __expf(s4[i][2] - m_new);
            float p3 = __expf(s4[i][3] - m_new);

            float rs = p0 + p1 + p2 + p3;
            rs += __shfl_xor_sync(0xffffffffu, rs, 1);
            rs += __shfl_xor_sync(0xffffffffu, rs, 2);
            rs += __shfl_xor_sync(0xffffffffu, rs, 4);
            rs += __shfl_xor_sync(0xffffffffu, rs, 8);

            float sc = __expf(m_r[i] - m_new);
            l_r[i] = l_r[i] * sc + rs;
            m_r[i] = m_new;
#pragma unroll
            for (int c = 0; c < 8; c++) o[i][c] *= sc;

            *(float4*)(sP + (ty * 4 + i) * 64 + tx * 4) = make_float4(p0, p1, p2, p3);
        }
        __syncthreads();

        // O += P @ V  (rows ty*4.., cols tx*8..)
#pragma unroll 2
        for (int j = 0; j < 64; j++) {
            float4 v0 = *(const float4*)(sV + j * 128 + tx * 8);
            float4 v1 = *(const float4*)(sV + j * 128 + tx * 8 + 4);
            float vv[8] = {v0.x, v0.y, v0.z, v0.w, v1.x, v1.y, v1.z, v1.w};
#pragma unroll
            for (int i = 0; i < 4; i++) {
                float p = sP[(ty * 4 + i) * 64 + j];
#pragma unroll
                for (int c = 0; c < 8; c++)
                    o[i][c] = fmaf(p, vv[c], o[i][c]);
            }
        }
    }

    // Epilogue: normalize and write ctx[b, q, h, d] as [R, 2048]
#pragma unroll
    for (int i = 0; i < 4; i++) {
        float inv = 1.0f / l_r[i];
        int grow  = qtile * 64 + ty * 4 + i;
        size_t off = (rowbase + (size_t)grow) * Mdim + (size_t)h * Ddim + tx * 8;
        float4 w0 = make_float4(o[i][0] * inv, o[i][1] * inv, o[i][2] * inv, o[i][3] * inv);
        float4 w1 = make_float4(o[i][4] * inv, o[i][5] * inv, o[i][6] * inv, o[i][7] * inv);
        *(float4*)(ctx + off)     = w0;
        *(float4*)(ctx + off + 4) = w1;
    }
}

// ---------------------------------------------------------------------------
extern "C" void kernel_launch(void* const* d_in, const int* in_sizes, int n_in,
                              void* d_out, int out_size) {
    const float* x    = (const float*)d_in[0];   // [B,S,M]
    const float* Wqkv = (const float*)d_in[1];   // [M,3,H,D] == [K=2048, N=6144]
    const float* Wo   = (const float*)d_in[2];   // [H*D, M] == [K=2048, N=2048]
    float* out = (float*)d_out;

    float *qkv = nullptr, *ctx = nullptr;
    cudaGetSymbolAddress((void**)&qkv, g_qkv);
    cudaGetSymbolAddress((void**)&ctx, g_ctx);

    cudaFuncSetAttribute(flash_attn, cudaFuncAttributeMaxDynamicSharedMemorySize,
                         FLASH_SMEM_BYTES);

    dim3 blk(256);

    // 1) qkv = x @ Wqkv   : [8192,2048]@[2048,6144]
    sgemm<<<dim3(N_QKV / GBN, Rrows / GBM), blk>>>(x, Wqkv, qkv, N_QKV, Mdim);

    // 2) RoPE on q,k in place
    rope_kernel<<<(Rrows * Hdim * (Ddim / 2)) / 256, blk>>>(qkv);

    // 3) causal flash attention -> ctx [8192, 2048]
    flash_attn<<<dim3(Sdim / 64, Bdim * Hdim), blk, FLASH_SMEM_BYTES>>>(qkv, ctx);

    // 4) out = ctx @ Wo : [8192,2048]@[2048,2048]
    sgemm<<<dim3(Mdim / GBN, Rrows / GBM), blk>>>(ctx, Wo, out, Mdim, Mdim);
}

// round 3
// speedup vs baseline: 1.7338x; 1.7338x over previous
#include <cuda_runtime.h>
#include <cuda_bf16.h>
#include <math.h>
#include <stdint.h>

#define Bdim 4
#define Sdim 2048
#define Mdim 2048
#define Hdim 16
#define Ddim 128
#define Rrows (Bdim * Sdim)          // 8192
#define N_QKV (3 * Hdim * Ddim)      // 6144

// Scratch (allocation-free rule: __device__ globals)
__device__ float g_qkv[(size_t)Rrows * N_QKV];                 // ~201 MB
__device__ __nv_bfloat16 g_xh[(size_t)Rrows * Mdim];           // x hi
__device__ __nv_bfloat16 g_xl[(size_t)Rrows * Mdim];           // x lo
__device__ __nv_bfloat16 g_wqh[(size_t)N_QKV * Mdim];          // Wqkv^T hi (K-major)
__device__ __nv_bfloat16 g_wql[(size_t)N_QKV * Mdim];          // Wqkv^T lo
__device__ __nv_bfloat16 g_woh[(size_t)Mdim * Mdim];           // Wo^T hi
__device__ __nv_bfloat16 g_wol[(size_t)Mdim * Mdim];           // Wo^T lo
__device__ __nv_bfloat16 g_ch[(size_t)Rrows * Mdim];           // ctx hi
__device__ __nv_bfloat16 g_cl[(size_t)Rrows * Mdim];           // ctx lo

// ============================ helpers ============================
__device__ __forceinline__ uint32_t smem_u32(const void* p) {
    uint32_t a;
    asm("{ .reg .u64 t; cvta.to.shared.u64 t, %1; cvt.u32.u64 %0, t; }"
        : "=r"(a) : "l"(p));
    return a;
}

__device__ __forceinline__ void cp_async16(uint32_t dst, const void* src) {
    asm volatile("cp.async.cg.shared.global [%0], [%1], 16;" :: "r"(dst), "l"(src));
}
#define CP_COMMIT() asm volatile("cp.async.commit_group;" ::: "memory")
#define CP_WAIT0()  asm volatile("cp.async.wait_group 0;" ::: "memory")
#define CP_WAIT1()  asm volatile("cp.async.wait_group 1;" ::: "memory")

#define LDSM_X4(r0, r1, r2, r3, addr)                                        \
    asm volatile("ldmatrix.sync.aligned.m8n8.x4.shared.b16 {%0,%1,%2,%3}, [%4];" \
        : "=r"(r0), "=r"(r1), "=r"(r2), "=r"(r3) : "r"(addr))

#define MMA_BF16(c, a, b)                                                    \
    asm volatile("mma.sync.aligned.m16n8k16.row.col.f32.bf16.bf16.f32 "      \
        "{%0,%1,%2,%3}, {%4,%5,%6,%7}, {%8,%9}, {%0,%1,%2,%3};"              \
        : "+f"((c)[0]), "+f"((c)[1]), "+f"((c)[2]), "+f"((c)[3])             \
        : "r"((a)[0]), "r"((a)[1]), "r"((a)[2]), "r"((a)[3]),                \
          "r"((b)[0]), "r"((b)[1]))

__device__ __forceinline__ unsigned pack2(__nv_bfloat16 a, __nv_bfloat16 b) {
    return (unsigned)__bfloat16_as_ushort(a) |
           ((unsigned)__bfloat16_as_ushort(b) << 16);
}

// ============================ split / transpose ============================
// x fp32 -> hi/lo bf16 (elementwise, float4 vectorized)
__global__ void split_fp32(const float* __restrict__ in,
                           __nv_bfloat16* __restrict__ hi,
                           __nv_bfloat16* __restrict__ lo) {
    unsigned i = blockIdx.x * blockDim.x + threadIdx.x;
    float4 v = ((const float4*)in)[i];
    float xs[4] = {v.x, v.y, v.z, v.w};
    __nv_bfloat16 h[4], l[4];
#pragma unroll
    for (int j = 0; j < 4; j++) {
        h[j] = __float2bfloat16(xs[j]);
        l[j] = __float2bfloat16(xs[j] - __bfloat162float(h[j]));
    }
    ((uint2*)hi)[i] = make_uint2(pack2(h[0], h[1]), pack2(h[2], h[3]));
    ((uint2*)lo)[i] = make_uint2(pack2(l[0], l[1]), pack2(l[2], l[3]));
}

// out_hi/lo[c][r] = split(in[r][c]); grid (cols/32, rows/32), block (32,8)
__global__ void transpose_split(const float* __restrict__ in,
                                __nv_bfloat16* __restrict__ hi,
                                __nv_bfloat16* __restrict__ lo,
                                int rows, int cols) {
    __shared__ float t[32][33];
    int x = blockIdx.x * 32 + threadIdx.x;
    int y = blockIdx.y * 32 + threadIdx.y;
#pragma unroll
    for (int j = 0; j < 32; j += 8)
        t[threadIdx.y + j][threadIdx.x] = in[(size_t)(y + j) * cols + x];
    __syncthreads();
    int x2 = blockIdx.y * 32 + threadIdx.x;
    int y2 = blockIdx.x * 32 + threadIdx.y;
#pragma unroll
    for (int j = 0; j < 32; j += 8) {
        float v = t[threadIdx.x][threadIdx.y + j];
        __nv_bfloat16 h = __float2bfloat16(v);
        __nv_bfloat16 l = __float2bfloat16(v - __bfloat162float(h));
        hi[(size_t)(y2 + j) * rows + x2] = h;
        lo[(size_t)(y2 + j) * rows + x2] = l;
    }
}

// ============================ 3xBF16 GEMM ============================
// C[M, Nc] = A[M, K] @ Bt[Nc, K]^T, A/B given as bf16 hi+lo pairs (K-major).
// CTA 128x128, BK=32, 8 warps (2x4), warp tile 64x32, mma.m16n8k16.
#define BM 128
#define BN 128
#define BK 32
#define TILE_BYTES  (128 * 32 * 2)            // 8192
#define STAGE_BYTES (4 * TILE_BYTES)          // 32768
#define GEMM_SMEM   (2 * STAGE_BYTES)         // 65536

__device__ __forceinline__ void gemm_issue(
    uint32_t sb,
    const __nv_bfloat16* __restrict__ Ah, const __nv_bfloat16* __restrict__ Al,
    const __nv_bfloat16* __restrict__ Bh, const __nv_bfloat16* __restrict__ Bl,
    int m0, int n0, int k0, int K, int tid) {
#pragma unroll
    for (int i = 0; i < 2; i++) {
        int f = i * 256 + tid;                 // 0..511
        int r = f >> 2, c = f & 3;             // row 0..127, 16B-chunk 0..3
        uint32_t off = (uint32_t)(r * 64 + ((c ^ (r & 3)) << 4));
        size_t ga = (size_t)(m0 + r) * K + k0 + c * 8;
        size_t gb = (size_t)(n0 + r) * K + k0 + c * 8;
        cp_async16(sb + off,                  Ah + ga);
        cp_async16(sb + TILE_BYTES + off,     Al + ga);
        cp_async16(sb + 2 * TILE_BYTES + off, Bh + gb);
        cp_async16(sb + 3 * TILE_BYTES + off, Bl + gb);
    }
}

__global__ __launch_bounds__(256)
void gemm_bf16x3(const __nv_bfloat16* __restrict__ Ah,
                 const __nv_bfloat16* __restrict__ Al,
                 const __nv_bfloat16* __restrict__ Bh,
                 const __nv_bfloat16* __restrict__ Bl,
                 float* __restrict__ C, int Nc, int K) {
    extern __shared__ char smem[];
    const uint32_t sbase = smem_u32(smem);
    const int tid  = threadIdx.x;
    const int wid  = tid >> 5, lane = tid & 31;
    const int wm   = wid & 1,  wn   = wid >> 1;
    const int m0   = blockIdx.y * BM, n0 = blockIdx.x * BN;

    float acc[4][4][4];
#pragma unroll
    for (int a = 0; a < 4; a++)
#pragma unroll
        for (int b = 0; b < 4; b++)
#pragma unroll
            for (int c = 0; c < 4; c++) acc[a][b][c] = 0.f;

    gemm_issue(sbase,               Ah, Al, Bh, Bl, m0, n0, 0,  K, tid);
    CP_COMMIT();
    gemm_issue(sbase + STAGE_BYTES, Ah, Al, Bh, Bl, m0, n0, BK, K, tid);
    CP_COMMIT();

    const int T = K / BK;
    for (int t = 0; t < T; t++) {
        if (t < T - 2) CP_WAIT1(); else CP_WAIT0();
        __syncthreads();
        const uint32_t sb = sbase + (t & 1) * STAGE_BYTES;

#pragma unroll
        for (int s = 0; s < 2; s++) {          // two k16 steps per stage
            // B fragments (hi & lo): 4 n-tiles x 2 regs each
            uint32_t bh[4][2], bl[4][2];
#pragma unroll
            for (int g = 0; g < 2; g++) {
                int nrow = wn * 32 + g * 16 + (lane & 7) + ((lane >> 4) << 3);
                int kc   = s * 2 + ((lane >> 3) & 1);
                uint32_t addr = sb + 2 * TILE_BYTES +
                                (uint32_t)(nrow * 64 + ((kc ^ (lane & 3)) << 4));
                LDSM_X4(bh[2*g][0], bh[2*g][1], bh[2*g+1][0], bh[2*g+1][1], addr);
                LDSM_X4(bl[2*g][0], bl[2*g][1], bl[2*g+1][0], bl[2*g+1][1],
                        addr + TILE_BYTES);
            }
            // A hi fragments: 4 m-tiles x 4 regs
            {
                uint32_t ah[4][4];
#pragma unroll
                for (int mt = 0; mt < 4; mt++) {
                    int r  = wm * 64 + mt * 16 + (lane & 15);
                    int kc = s * 2 + (lane >> 4);
                    uint32_t addr = sb +
                        (uint32_t)(r * 64 + ((kc ^ (lane & 3)) << 4));
                    LDSM_X4(ah[mt][0], ah[mt][1], ah[mt][2], ah[mt][3], addr);
                }
#pragma unroll
                for (int mt = 0; mt < 4; mt++)
#pragma unroll
                    for (int nt = 0; nt < 4; nt++) {
                        MMA_BF16(acc[mt][nt], ah[mt], bh[nt]);
                        MMA_BF16(acc[mt][nt], ah[mt], bl[nt]);
                    }
            }
            // A lo fragments (reuse regs)
            {
                uint32_t al_[4][4];
#pragma unroll
                for (int mt = 0; mt < 4; mt++) {
                    int r  = wm * 64 + mt * 16 + (lane & 15);
                    int kc = s * 2 + (lane >> 4);
                    uint32_t addr = sb + TILE_BYTES +
                        (uint32_t)(r * 64 + ((kc ^ (lane & 3)) << 4));
                    LDSM_X4(al_[mt][0], al_[mt][1], al_[mt][2], al_[mt][3], addr);
                }
#pragma unroll
                for (int mt = 0; mt < 4; mt++)
#pragma unroll
                    for (int nt = 0; nt < 4; nt++)
                        MMA_BF16(acc[mt][nt], al_[mt], bh[nt]);
            }
        }
        __syncthreads();
        if (t + 2 < T) {
            gemm_issue(sbase + (t & 1) * STAGE_BYTES, Ah, Al, Bh, Bl,
                       m0, n0, (t + 2) * BK, K, tid);
            CP_COMMIT();
        }
    }

    // Epilogue: c0,c1 = (row T/4, cols 2(T%4)+{0,1}); c2,c3 = row+8
#pragma unroll
    for (int mt = 0; mt < 4; mt++)
#pragma unroll
        for (int nt = 0; nt < 4; nt++) {
            int row = m0 + wm * 64 + mt * 16 + (lane >> 2);
            int col = n0 + wn * 32 + nt * 8 + 2 * (lane & 3);
            *(float2*)(C + (size_t)row * Nc + col) =
                make_float2(acc[mt][nt][0], acc[mt][nt][1]);
            *(float2*)(C + (size_t)(row + 8) * Nc + col) =
                make_float2(acc[mt][nt][2], acc[mt][nt][3]);
        }
}

// ============================ RoPE (unchanged) ============================
__global__ void rope_kernel(float* __restrict__ qkv) {
    unsigned idx = blockIdx.x * blockDim.x + threadIdx.x;
    int pair = idx & 63;
    int h    = (idx >> 6) & 15;
    unsigned r = idx >> 10;
    int s = (int)(r & (Sdim - 1));

    double frac  = (double)(2 * pair) / (double)Ddim;
    double theta = (double)s * exp(-frac * 9.210340371976184);
    double sd, cd;
    sincos(theta, &sd, &cd);
    float sn = (float)sd, cs = (float)cd;

    size_t base = (size_t)r * N_QKV + (size_t)h * Ddim + 2 * pair;

    float2 q = *(float2*)(qkv + base);
    float2 qo;
    qo.x = fmaf(q.x, cs, -q.y * sn);
    qo.y = fmaf(q.y, cs,  q.x * sn);
    *(float2*)(qkv + base) = qo;

    size_t kb = base + 2048;
    float2 k = *(float2*)(qkv + kb);
    float2 ko;
    ko.x = fmaf(k.x, cs, -k.y * sn);
    ko.y = fmaf(k.y, cs,  k.x * sn);
    *(float2*)(qkv + kb) = ko;
}

// ======================= Flash attention (epilogue -> bf16 hi/lo) =======================
#define FLASH_SMEM_FLOATS (128 * 64 + 128 * 64 + 64 * 128 + 64 * 64)
#define FLASH_SMEM_BYTES  (FLASH_SMEM_FLOATS * 4)

__global__ __launch_bounds__(256)
void flash_attn(const float* __restrict__ qkv,
                __nv_bfloat16* __restrict__ ctx_hi,
                __nv_bfloat16* __restrict__ ctx_lo) {
    const int qtile = blockIdx.x;
    const int b     = blockIdx.y >> 4;
    const int h     = blockIdx.y & 15;

    extern __shared__ float sm[];
    float* sQt = sm;
    float* sKt = sm + 8192;
    float* sV  = sm + 16384;
    float* sP  = sm + 24576;

    const int tid = threadIdx.x;
    const int ty  = tid >> 4;
    const int tx  = tid & 15;

    const size_t rowbase = (size_t)(b * Sdim);
    const size_t qbase   = (rowbase + (size_t)qtile * 64) * N_QKV + (size_t)h * Ddim;

#pragma unroll
    for (int i = 0; i < 8; i++) {
        int f   = i * 256 + tid;
        int lo  = f & 3;
        int mid = (f >> 2) & 63;
        int hi  = f >> 8;
        int row = mid;
        int dc  = hi * 16 + lo * 4;
        float4 v = *(const float4*)(qkv + qbase + (size_t)row * N_QKV + dc);
        sQt[(dc + 0) * 64 + row] = v.x;
        sQt[(dc + 1) * 64 + row] = v.y;
        sQt[(dc + 2) * 64 + row] = v.z;
        sQt[(dc + 3) * 64 + row] = v.w;
    }

    float m_r[4], l_r[4], o[4][8];
#pragma unroll
    for (int i = 0; i < 4; i++) { m_r[i] = -1e30f; l_r[i] = 0.f; }
#pragma unroll
    for (int i = 0; i < 4; i++)
#pragma unroll
        for (int j = 0; j < 8; j++) o[i][j] = 0.f;

    const float scale = 0.08838834764831845f;

    for (int kt = 0; kt <= qtile; kt++) {
        __syncthreads();

        const size_t kb = (rowbase + (size_t)kt * 64) * N_QKV + (size_t)h * Ddim + 2048;
        const size_t vb = kb + 2048;

#pragma unroll
        for (int i = 0; i < 8; i++) {
            int f   = i * 256 + tid;
            int lo  = f & 3;
            int mid = (f >> 2) & 63;
            int hi  = f >> 8;
            int row = mid;
            int dc  = hi * 16 + lo * 4;
            float4 v = *(const float4*)(qkv + kb + (size_t)row * N_QKV + dc);
            sKt[(dc + 0) * 64 + row] = v.x;
            sKt[(dc + 1) * 64 + row] = v.y;
            sKt[(dc + 2) * 64 + row] = v.z;
            sKt[(dc + 3) * 64 + row] = v.w;
        }
#pragma unroll
        for (int i = 0; i < 8; i++) {
            int f   = i * 256 + tid;
            int row = f >> 5;
            int c4  = (f & 31) << 2;
            *(float4*)(sV + row * 128 + c4) =
                *(const float4*)(qkv + vb + (size_t)row * N_QKV + c4);
        }
        __syncthreads();

        float s4[4][4];
#pragma unroll
        for (int i = 0; i < 4; i++)
#pragma unroll
            for (int j = 0; j < 4; j++) s4[i][j] = 0.f;

#pragma unroll 8
        for (int kk = 0; kk < 128; kk++) {
            float4 a  = *(const float4*)(sQt + kk * 64 + ty * 4);
            float4 bk = *(const float4*)(sKt + kk * 64 + tx * 4);
            float av[4] = {a.x, a.y, a.z, a.w};
            float bv[4] = {bk.x, bk.y, bk.z, bk.w};
#pragma unroll
            for (int i = 0; i < 4; i++)
#pragma unroll
                for (int j = 0; j < 4; j++)
                    s4[i][j] = fmaf(av[i], bv[j], s4[i][j]);
        }

        const bool diag = (kt == qtile);
#pragma unroll
        for (int i = 0; i < 4; i++) {
            int qi = ty * 4 + i;
#pragma unroll
            for (int j = 0; j < 4; j++) {
                int kj = tx * 4 + j;
                if (diag && kj > qi) s4[i][j] = -1e30f;
                else                 s4[i][j] *= scale;
            }
        }

#pragma unroll
        for (int i = 0; i < 4; i++) {
            float mx = fmaxf(fmaxf(s4[i][0], s4[i][1]), fmaxf(s4[i][2], s4[i][3]));
            mx = fmaxf(mx, __shfl_xor_sync(0xffffffffu, mx, 1));
            mx = fmaxf(mx, __shfl_xor_sync(0xffffffffu, mx, 2));
            mx = fmaxf(mx, __shfl_xor_sync(0xffffffffu, mx, 4));
            mx = fmaxf(mx, __shfl_xor_sync(0xffffffffu, mx, 8));
            float m_new = fmaxf(m_r[i], mx);

            float p0 = __expf(s4[i][0] - m_new);
            float p1 = __expf(s4[i][1] - m_new);
            float p2 = __expf(s4[i][2] - m_new);
            float p3 = __expf(s4[i][3] - m_new);

            float rs = p0 + p1 + p2 + p3;
            rs += __shfl_xor_sync(0xffffffffu, rs, 1);
            rs += __shfl_xor_sync(0xffffffffu, rs, 2);
            rs += __shfl_xor_sync(0xffffffffu, rs, 4);
            rs += __shfl_xor_sync(0xffffffffu, rs, 8);

            float sc = __expf(m_r[i] - m_new);
            l_r[i] = l_r[i] * sc + rs;
            m_r[i] = m_new;
#pragma unroll
            for (int c = 0; c < 8; c++) o[i][c] *= sc;

            *(float4*)(sP + (ty * 4 + i) * 64 + tx * 4) = make_float4(p0, p1, p2, p3);
        }
        __syncthreads();

#pragma unroll 2
        for (int j = 0; j < 64; j++) {
            float4 v0 = *(const float4*)(sV + j * 128 + tx * 8);
            float4 v1 = *(const float4*)(sV + j * 128 + tx * 8 + 4);
            float vv[8] = {v0.x, v0.y, v0.z, v0.w, v1.x, v1.y, v1.z, v1.w};
#pragma unroll
            for (int i = 0; i < 4; i++) {
                float p = sP[(ty * 4 + i) * 64 + j];
#pragma unroll
                for (int c = 0; c < 8; c++)
                    o[i][c] = fmaf(p, vv[c], o[i][c]);
            }
        }
    }

    // Epilogue: normalize, split into bf16 hi/lo, write 16B each
#pragma unroll
    for (int i = 0; i < 4; i++) {
        float inv = 1.0f / l_r[i];
        int grow  = qtile * 64 + ty * 4 + i;
        size_t off = (rowbase + (size_t)grow) * Mdim + (size_t)h * Ddim + tx * 8;
        unsigned hb[4], lb[4];
#pragma unroll
        for (int c = 0; c < 4; c++) {
            float v0 = o[i][2 * c] * inv;
            float v1 = o[i][2 * c + 1] * inv;
            __nv_bfloat16 h0 = __float2bfloat16(v0);
            __nv_bfloat16 h1 = __float2bfloat16(v1);
            __nv_bfloat16 l0 = __float2bfloat16(v0 - __bfloat162float(h0));
            __nv_bfloat16 l1 = __float2bfloat16(v1 - __bfloat162float(h1));
            hb[c] = pack2(h0, h1);
            lb[c] = pack2(l0, l1);
        }
        *(uint4*)(ctx_hi + off) = make_uint4(hb[0], hb[1], hb[2], hb[3]);
        *(uint4*)(ctx_lo + off) = make_uint4(lb[0], lb[1], lb[2], lb[3]);
    }
}

// ---------------------------------------------------------------------------
extern "C" void kernel_launch(void* const* d_in, const int* in_sizes, int n_in,
                              void* d_out, int out_size) {
    const float* x    = (const float*)d_in[0];   // [8192, 2048]
    const float* Wqkv = (const float*)d_in[1];   // [2048, 6144]
    const float* Wo   = (const float*)d_in[2];   // [2048, 2048]
    float* out = (float*)d_out;

    float* qkv = nullptr;
    __nv_bfloat16 *xh, *xl, *wqh, *wql, *woh, *wol, *ch, *cl;
    cudaGetSymbolAddress((void**)&qkv, g_qkv);
    cudaGetSymbolAddress((void**)&xh,  g_xh);
    cudaGetSymbolAddress((void**)&xl,  g_xl);
    cudaGetSymbolAddress((void**)&wqh, g_wqh);
    cudaGetSymbolAddress((void**)&wql, g_wql);
    cudaGetSymbolAddress((void**)&woh, g_woh);
    cudaGetSymbolAddress((void**)&wol, g_wol);
    cudaGetSymbolAddress((void**)&ch,  g_ch);
    cudaGetSymbolAddress((void**)&cl,  g_cl);

    cudaFuncSetAttribute(gemm_bf16x3, cudaFuncAttributeMaxDynamicSharedMemorySize,
                         GEMM_SMEM);
    cudaFuncSetAttribute(flash_attn, cudaFuncAttributeMaxDynamicSharedMemorySize,
                         FLASH_SMEM_BYTES);

    // 0) prepare operands: transpose+split weights, split x
    transpose_split<<<dim3(N_QKV / 32, Mdim / 32), dim3(32, 8)>>>(Wqkv, wqh, wql,
                                                                  Mdim, N_QKV);
    transpose_split<<<dim3(Mdim / 32, Mdim / 32), dim3(32, 8)>>>(Wo, woh, wol,
                                                                 Mdim, Mdim);
    split_fp32<<<((size_t)Rrows * Mdim / 4) / 256, 256>>>(x, xh, xl);

    // 1) qkv = x @ Wqkv  (3xBF16 tensor-core GEMM)
    gemm_bf16x3<<<dim3(N_QKV / BN, Rrows / BM), 256, GEMM_SMEM>>>(
        xh, xl, wqh, wql, qkv, N_QKV, Mdim);

    // 2) RoPE in place
    rope_kernel<<<(Rrows * Hdim * (Ddim / 2)) / 256, 256>>>(qkv);

    // 3) causal flash attention -> ctx (bf16 hi/lo)
    flash_attn<<<dim3(Sdim / 64, Bdim * Hdim), 256, FLASH_SMEM_BYTES>>>(qkv, ch, cl);

    // 4) out = ctx @ Wo  (3xBF16 tensor-core GEMM)
    gemm_bf16x3<<<dim3(Mdim / BN, Rrows / BM), 256, GEMM_SMEM>>>(
        ch, cl, woh, wol, out, Mdim, Mdim);
}

// round 4
// speedup vs baseline: 2.7028x; 1.5589x over previous
#include <cuda_runtime.h>
#include <cuda_bf16.h>
#include <math.h>
#include <stdint.h>

#define Bdim 4
#define Sdim 2048
#define Mdim 2048
#define Hdim 16
#define Ddim 128
#define Rrows (Bdim * Sdim)          // 8192
#define N_QKV (3 * Hdim * Ddim)      // 6144
#define BH (Bdim * Hdim)             // 64

// Scratch (allocation-free rule: __device__ globals)
__device__ float g_qkv[(size_t)Rrows * N_QKV];                 // ~201 MB
__device__ __nv_bfloat16 g_xh[(size_t)Rrows * Mdim];
__device__ __nv_bfloat16 g_xl[(size_t)Rrows * Mdim];
__device__ __nv_bfloat16 g_wqh[(size_t)N_QKV * Mdim];
__device__ __nv_bfloat16 g_wql[(size_t)N_QKV * Mdim];
__device__ __nv_bfloat16 g_woh[(size_t)Mdim * Mdim];
__device__ __nv_bfloat16 g_wol[(size_t)Mdim * Mdim];
__device__ __nv_bfloat16 g_ch[(size_t)Rrows * Mdim];
__device__ __nv_bfloat16 g_cl[(size_t)Rrows * Mdim];
// attention operands (bf16 hi/lo)
__device__ __nv_bfloat16 g_qh[(size_t)BH * Sdim * Ddim];       // [bh][s][d]
__device__ __nv_bfloat16 g_ql[(size_t)BH * Sdim * Ddim];
__device__ __nv_bfloat16 g_kh[(size_t)BH * Sdim * Ddim];
__device__ __nv_bfloat16 g_kl[(size_t)BH * Sdim * Ddim];
__device__ __nv_bfloat16 g_vh[(size_t)BH * Ddim * Sdim];       // [bh][d][s]  (V^T)
__device__ __nv_bfloat16 g_vl[(size_t)BH * Ddim * Sdim];

// ============================ helpers ============================
__device__ __forceinline__ uint32_t smem_u32(const void* p) {
    uint32_t a;
    asm("{ .reg .u64 t; cvta.to.shared.u64 t, %1; cvt.u32.u64 %0, t; }"
        : "=r"(a) : "l"(p));
    return a;
}

__device__ __forceinline__ void cp_async16(uint32_t dst, const void* src) {
    asm volatile("cp.async.cg.shared.global [%0], [%1], 16;" :: "r"(dst), "l"(src));
}
#define CP_COMMIT() asm volatile("cp.async.commit_group;" ::: "memory")
#define CP_WAIT0()  asm volatile("cp.async.wait_group 0;" ::: "memory")
#define CP_WAIT1()  asm volatile("cp.async.wait_group 1;" ::: "memory")

#define LDSM_X4(r0, r1, r2, r3, addr)                                        \
    asm volatile("ldmatrix.sync.aligned.m8n8.x4.shared.b16 {%0,%1,%2,%3}, [%4];" \
        : "=r"(r0), "=r"(r1), "=r"(r2), "=r"(r3) : "r"(addr))

#define MMA_BF16(c, a, b)                                                    \
    asm volatile("mma.sync.aligned.m16n8k16.row.col.f32.bf16.bf16.f32 "      \
        "{%0,%1,%2,%3}, {%4,%5,%6,%7}, {%8,%9}, {%0,%1,%2,%3};"              \
        : "+f"((c)[0]), "+f"((c)[1]), "+f"((c)[2]), "+f"((c)[3])             \
        : "r"((a)[0]), "r"((a)[1]), "r"((a)[2]), "r"((a)[3]),                \
          "r"((b)[0]), "r"((b)[1]))

__device__ __forceinline__ unsigned pack2(__nv_bfloat16 a, __nv_bfloat16 b) {
    return (unsigned)__bfloat16_as_ushort(a) |
           ((unsigned)__bfloat16_as_ushort(b) << 16);
}

// ============================ split / transpose prep ============================
__global__ void split_fp32(const float* __restrict__ in,
                           __nv_bfloat16* __restrict__ hi,
                           __nv_bfloat16* __restrict__ lo) {
    unsigned i = blockIdx.x * blockDim.x + threadIdx.x;
    float4 v = ((const float4*)in)[i];
    float xs[4] = {v.x, v.y, v.z, v.w};
    __nv_bfloat16 h[4], l[4];
#pragma unroll
    for (int j = 0; j < 4; j++) {
        h[j] = __float2bfloat16(xs[j]);
        l[j] = __float2bfloat16(xs[j] - __bfloat162float(h[j]));
    }
    ((uint2*)hi)[i] = make_uint2(pack2(h[0], h[1]), pack2(h[2], h[3]));
    ((uint2*)lo)[i] = make_uint2(pack2(l[0], l[1]), pack2(l[2], l[3]));
}

__global__ void transpose_split(const float* __restrict__ in,
                                __nv_bfloat16* __restrict__ hi,
                                __nv_bfloat16* __restrict__ lo,
                                int rows, int cols) {
    __shared__ float t[32][33];
    int x = blockIdx.x * 32 + threadIdx.x;
    int y = blockIdx.y * 32 + threadIdx.y;
#pragma unroll
    for (int j = 0; j < 32; j += 8)
        t[threadIdx.y + j][threadIdx.x] = in[(size_t)(y + j) * cols + x];
    __syncthreads();
    int x2 = blockIdx.y * 32 + threadIdx.x;
    int y2 = blockIdx.x * 32 + threadIdx.y;
#pragma unroll
    for (int j = 0; j < 32; j += 8) {
        float v = t[threadIdx.x][threadIdx.y + j];
        __nv_bfloat16 h = __float2bfloat16(v);
        __nv_bfloat16 l = __float2bfloat16(v - __bfloat162float(h));
        hi[(size_t)(y2 + j) * rows + x2] = h;
        lo[(size_t)(y2 + j) * rows + x2] = l;
    }
}

// ============================ 3xBF16 GEMM (as R3) ============================
#define BM 128
#define BN 128
#define BK 32
#define TILE_BYTES  (128 * 32 * 2)
#define STAGE_BYTES (4 * TILE_BYTES)
#define GEMM_SMEM   (2 * STAGE_BYTES)

__device__ __forceinline__ void gemm_issue(
    uint32_t sb,
    const __nv_bfloat16* __restrict__ Ah, const __nv_bfloat16* __restrict__ Al,
    const __nv_bfloat16* __restrict__ Bh, const __nv_bfloat16* __restrict__ Bl,
    int m0, int n0, int k0, int K, int tid) {
#pragma unroll
    for (int i = 0; i < 2; i++) {
        int f = i * 256 + tid;
        int r = f >> 2, c = f & 3;
        uint32_t off = (uint32_t)(r * 64 + ((c ^ (r & 3)) << 4));
        size_t ga = (size_t)(m0 + r) * K + k0 + c * 8;
        size_t gb = (size_t)(n0 + r) * K + k0 + c * 8;
        cp_async16(sb + off,                  Ah + ga);
        cp_async16(sb + TILE_BYTES + off,     Al + ga);
        cp_async16(sb + 2 * TILE_BYTES + off, Bh + gb);
        cp_async16(sb + 3 * TILE_BYTES + off, Bl + gb);
    }
}

__global__ __launch_bounds__(256)
void gemm_bf16x3(const __nv_bfloat16* __restrict__ Ah,
                 const __nv_bfloat16* __restrict__ Al,
                 const __nv_bfloat16* __restrict__ Bh,
                 const __nv_bfloat16* __restrict__ Bl,
                 float* __restrict__ C, int Nc, int K) {
    extern __shared__ char smem[];
    const uint32_t sbase = smem_u32(smem);
    const int tid  = threadIdx.x;
    const int wid  = tid >> 5, lane = tid & 31;
    const int wm   = wid & 1,  wn   = wid >> 1;
    const int m0   = blockIdx.y * BM, n0 = blockIdx.x * BN;

    float acc[4][4][4];
#pragma unroll
    for (int a = 0; a < 4; a++)
#pragma unroll
        for (int b = 0; b < 4; b++)
#pragma unroll
            for (int c = 0; c < 4; c++) acc[a][b][c] = 0.f;

    gemm_issue(sbase,               Ah, Al, Bh, Bl, m0, n0, 0,  K, tid);
    CP_COMMIT();
    gemm_issue(sbase + STAGE_BYTES, Ah, Al, Bh, Bl, m0, n0, BK, K, tid);
    CP_COMMIT();

    const int T = K / BK;
    for (int t = 0; t < T; t++) {
        if (t < T - 2) CP_WAIT1(); else CP_WAIT0();
        __syncthreads();
        const uint32_t sb = sbase + (t & 1) * STAGE_BYTES;

#pragma unroll
        for (int s = 0; s < 2; s++) {
            uint32_t bh[4][2], bl[4][2];
#pragma unroll
            for (int g = 0; g < 2; g++) {
                int nrow = wn * 32 + g * 16 + (lane & 7) + ((lane >> 4) << 3);
                int kc   = s * 2 + ((lane >> 3) & 1);
                uint32_t addr = sb + 2 * TILE_BYTES +
                                (uint32_t)(nrow * 64 + ((kc ^ (lane & 3)) << 4));
                LDSM_X4(bh[2*g][0], bh[2*g][1], bh[2*g+1][0], bh[2*g+1][1], addr);
                LDSM_X4(bl[2*g][0], bl[2*g][1], bl[2*g+1][0], bl[2*g+1][1],
                        addr + TILE_BYTES);
            }
            {
                uint32_t ah[4][4];
#pragma unroll
                for (int mt = 0; mt < 4; mt++) {
                    int r  = wm * 64 + mt * 16 + (lane & 15);
                    int kc = s * 2 + (lane >> 4);
                    uint32_t addr = sb +
                        (uint32_t)(r * 64 + ((kc ^ (lane & 3)) << 4));
                    LDSM_X4(ah[mt][0], ah[mt][1], ah[mt][2], ah[mt][3], addr);
                }
#pragma unroll
                for (int mt = 0; mt < 4; mt++)
#pragma unroll
                    for (int nt = 0; nt < 4; nt++) {
                        MMA_BF16(acc[mt][nt], ah[mt], bh[nt]);
                        MMA_BF16(acc[mt][nt], ah[mt], bl[nt]);
                    }
            }
            {
                uint32_t al_[4][4];
#pragma unroll
                for (int mt = 0; mt < 4; mt++) {
                    int r  = wm * 64 + mt * 16 + (lane & 15);
                    int kc = s * 2 + (lane >> 4);
                    uint32_t addr = sb + TILE_BYTES +
                        (uint32_t)(r * 64 + ((kc ^ (lane & 3)) << 4));
                    LDSM_X4(al_[mt][0], al_[mt][1], al_[mt][2], al_[mt][3], addr);
                }
#pragma unroll
                for (int mt = 0; mt < 4; mt++)
#pragma unroll
                    for (int nt = 0; nt < 4; nt++)
                        MMA_BF16(acc[mt][nt], al_[mt], bh[nt]);
            }
        }
        __syncthreads();
        if (t + 2 < T) {
            gemm_issue(sbase + (t & 1) * STAGE_BYTES, Ah, Al, Bh, Bl,
                       m0, n0, (t + 2) * BK, K, tid);
            CP_COMMIT();
        }
    }

#pragma unroll
    for (int mt = 0; mt < 4; mt++)
#pragma unroll
        for (int nt = 0; nt < 4; nt++) {
            int row = m0 + wm * 64 + mt * 16 + (lane >> 2);
            int col = n0 + wn * 32 + nt * 8 + 2 * (lane & 3);
            *(float2*)(C + (size_t)row * Nc + col) =
                make_float2(acc[mt][nt][0], acc[mt][nt][1]);
            *(float2*)(C + (size_t)(row + 8) * Nc + col) =
                make_float2(acc[mt][nt][2], acc[mt][nt][3]);
        }
}

// ============================ RoPE + split to attention layout ============================
__global__ void rope_split(const float* __restrict__ qkv,
                           __nv_bfloat16* __restrict__ qh, __nv_bfloat16* __restrict__ ql,
                           __nv_bfloat16* __restrict__ kh, __nv_bfloat16* __restrict__ kl) {
    unsigned idx = blockIdx.x * blockDim.x + threadIdx.x;
    int pair = idx & 63;
    int h    = (idx >> 6) & 15;
    unsigned r = idx >> 10;             // 0..8191
    int s = (int)(r & (Sdim - 1));
    int b = (int)(r >> 11);

    double frac  = (double)(2 * pair) / (double)Ddim;
    double theta = (double)s * exp(-frac * 9.210340371976184);
    double sd, cd;
    sincos(theta, &sd, &cd);
    float sn = (float)sd, cs = (float)cd;

    size_t src = (size_t)r * N_QKV + (size_t)h * Ddim + 2 * pair;
    size_t dst = ((size_t)(b * Hdim + h) * Sdim + s) * Ddim + 2 * pair;

    float2 q = *(const float2*)(qkv + src);
    float qx = fmaf(q.x, cs, -q.y * sn);
    float qy = fmaf(q.y, cs,  q.x * sn);
    __nv_bfloat16 hx = __float2bfloat16(qx), hy = __float2bfloat16(qy);
    *(unsigned*)(qh + dst) = pack2(hx, hy);
    *(unsigned*)(ql + dst) = pack2(__float2bfloat16(qx - __bfloat162float(hx)),
                                   __float2bfloat16(qy - __bfloat162float(hy)));

    float2 k = *(const float2*)(qkv + src + 2048);
    float kx = fmaf(k.x, cs, -k.y * sn);
    float ky = fmaf(k.y, cs,  k.x * sn);
    hx = __float2bfloat16(kx); hy = __float2bfloat16(ky);
    *(unsigned*)(kh + dst) = pack2(hx, hy);
    *(unsigned*)(kl + dst) = pack2(__float2bfloat16(kx - __bfloat162float(hx)),
                                   __float2bfloat16(ky - __bfloat162float(hy)));
}

// V -> V^T [bh][d][s] with hi/lo split. grid (S/32, H*4, B), block (32,8)
__global__ void vsplitT(const float* __restrict__ qkv,
                        __nv_bfloat16* __restrict__ vh,
                        __nv_bfloat16* __restrict__ vl) {
    __shared__ float t[32][33];
    int b  = blockIdx.z;
    int h  = blockIdx.y >> 2;
    int d0 = (blockIdx.y & 3) * 32;
    int s0 = blockIdx.x * 32;
#pragma unroll
    for (int j = 0; j < 32; j += 8)
        t[threadIdx.y + j][threadIdx.x] =
            qkv[(size_t)(b * Sdim + s0 + threadIdx.y + j) * N_QKV
                + 4096 + h * Ddim + d0 + threadIdx.x];
    __syncthreads();
#pragma unroll
    for (int j = 0; j < 32; j += 8) {
        float v = t[threadIdx.x][threadIdx.y + j];
        __nv_bfloat16 hh = __float2bfloat16(v);
        size_t o = ((size_t)((b * Hdim + h) * Ddim + d0 + threadIdx.y + j)) * Sdim
                   + s0 + threadIdx.x;
        vh[o] = hh;
        vl[o] = __float2bfloat16(v - __bfloat162float(hh));
    }
}

// ============================ Tensor-core flash attention ============================
// 128 q-rows per CTA, 64 k-cols per iteration, D=128. 8 warps x 16 q-rows.
// 3xBF16 on both QK^T and PV. Double-buffered cp.async K/V.
#define SQH_OFF 0
#define SQL_OFF 32768
#define SKH_OFF(st) (65536 + (st) * 32768)
#define SVH_OFF(st) (131072 + (st) * 32768)
#define ATT_SMEM 196608

__device__ __forceinline__ void att_issue_kv(
    uint32_t sb, int st, int kt, int bh, int tid,
    const __nv_bfloat16* __restrict__ kh, const __nv_bfloat16* __restrict__ kl,
    const __nv_bfloat16* __restrict__ vh, const __nv_bfloat16* __restrict__ vl) {
    const size_t krow0 = (size_t)bh * Sdim + kt * 64;
    const size_t vrow0 = (size_t)bh * Ddim;
#pragma unroll
    for (int i = 0; i < 4; i++) {           // K: 64 rows x 256B
        int f = i * 256 + tid;
        int r = f >> 4, c = f & 15;
        uint32_t off = (uint32_t)(r * 256 + ((c ^ (r & 7)) << 4));
        const __nv_bfloat16* sh = kh + (krow0 + r) * Ddim + c * 8;
        const __nv_bfloat16* sl = kl + (krow0 + r) * Ddim + c * 8;
        cp_async16(sb + SKH_OFF(st) + off,         sh);
        cp_async16(sb + SKH_OFF(st) + 16384 + off, sl);
    }
#pragma unroll
    for (int i = 0; i < 4; i++) {           // V^T: 128 rows x 128B
        int f = i * 256 + tid;
        int r = f >> 3, c = f & 7;
        uint32_t off = (uint32_t)(r * 128 + ((c ^ (r & 7)) << 4));
        const __nv_bfloat16* sh = vh + (vrow0 + r) * Sdim + kt * 64 + c * 8;
        const __nv_bfloat16* sl = vl + (vrow0 + r) * Sdim + kt * 64 + c * 8;
        cp_async16(sb + SVH_OFF(st) + off,         sh);
        cp_async16(sb + SVH_OFF(st) + 16384 + off, sl);
    }
}

__global__ __launch_bounds__(256, 1)
void flash_attn_tc(const __nv_bfloat16* __restrict__ qh, const __nv_bfloat16* __restrict__ ql,
                   const __nv_bfloat16* __restrict__ kh, const __nv_bfloat16* __restrict__ kl,
                   const __nv_bfloat16* __restrict__ vh, const __nv_bfloat16* __restrict__ vl,
                   __nv_bfloat16* __restrict__ ch, __nv_bfloat16* __restrict__ cl) {
    extern __shared__ char sm[];
    const uint32_t sb = smem_u32(sm);
    const int tid  = threadIdx.x;
    const int w    = tid >> 5, lane = tid & 31;
    const int qt   = (int)(gridDim.x - 1 - blockIdx.x);   // longest first
    const int bh   = blockIdx.y;
    const size_t qrow0 = (size_t)bh * Sdim + qt * 128;

    // Q tile (hi/lo) -> smem
#pragma unroll
    for (int i = 0; i < 8; i++) {
        int f = i * 256 + tid;
        int r = f >> 4, c = f & 15;
        uint32_t off = (uint32_t)(r * 256 + ((c ^ (r & 7)) << 4));
        cp_async16(sb + SQH_OFF + off, qh + (qrow0 + r) * Ddim + c * 8);
        cp_async16(sb + SQL_OFF + off, ql + (qrow0 + r) * Ddim + c * 8);
    }
    CP_COMMIT();

    const int nk = 2 * qt + 2;
    att_issue_kv(sb, 0, 0, bh, tid, kh, kl, vh, vl);
    CP_COMMIT();
    att_issue_kv(sb, 1, 1, bh, tid, kh, kl, vh, vl);
    CP_COMMIT();

    float o[16][4];
#pragma unroll
    for (int nt = 0; nt < 16; nt++)
#pragma unroll
        for (int c = 0; c < 4; c++) o[nt][c] = 0.f;
    float m0 = -1e30f, m1 = -1e30f, l0 = 0.f, l1 = 0.f;

    const float scale = 0.08838834764831845f;
    const int rg0 = qt * 128 + w * 16 + (lane >> 2);

    for (int kt = 0; kt < nk; kt++) {
        if (kt + 1 < nk) CP_WAIT1(); else CP_WAIT0();
        __syncthreads();
        const int st = kt & 1;
        const bool warp_live = (qt * 128 + w * 16 + 15) >= kt * 64;

        if (warp_live) {
            float s_acc[8][4];
#pragma unroll
            for (int j = 0; j < 8; j++)
#pragma unroll
                for (int c = 0; c < 4; c++) s_acc[j][c] = 0.f;

            // ---- S = Q K^T (3xBF16) ----
#pragma unroll
            for (int ks = 0; ks < 8; ks++) {
                uint32_t ah[4], al[4];
                {
                    int rA  = w * 16 + (lane & 15);
                    int kcA = 2 * ks + (lane >> 4);
                    uint32_t aoff = (uint32_t)(rA * 256 + ((kcA ^ (lane & 7)) << 4));
                    LDSM_X4(ah[0], ah[1], ah[2], ah[3], sb + SQH_OFF + aoff);
                    LDSM_X4(al[0], al[1], al[2], al[3], sb + SQL_OFF + aoff);
                }
#pragma unroll
                for (int g = 0; g < 4; g++) {
                    int nrow = g * 16 + (lane & 7) + ((lane >> 4) << 3);
                    int kc   = 2 * ks + ((lane >> 3) & 1);
                    uint32_t boff = (uint32_t)(nrow * 256 + ((kc ^ (lane & 7)) << 4));
                    uint32_t h0, h1, h2, h3, z0, z1, z2, z3;
                    LDSM_X4(h0, h1, h2, h3, sb + SKH_OFF(st) + boff);
                    LDSM_X4(z0, z1, z2, z3, sb + SKH_OFF(st) + 16384 + boff);
                    uint32_t bh0[2] = {h0, h1}, bh1[2] = {h2, h3};
                    uint32_t bl0[2] = {z0, z1}, bl1[2] = {z2, z3};
                    MMA_BF16(s_acc[2*g],   ah, bh0);
                    MMA_BF16(s_acc[2*g],   al, bh0);
                    MMA_BF16(s_acc[2*g],   ah, bl0);
                    MMA_BF16(s_acc[2*g+1], ah, bh1);
                    MMA_BF16(s_acc[2*g+1], al, bh1);
                    MMA_BF16(s_acc[2*g+1], ah, bl1);
                }
            }

            // ---- scale + causal mask ----
            const bool tile_masked = (kt * 64 + 63) > (qt * 128 + w * 16);
#pragma unroll
            for (int j = 0; j < 8; j++) {
                int cg = kt * 64 + 8 * j + 2 * (lane & 3);
                if (tile_masked) {
                    s_acc[j][0] = (cg     > rg0)     ? -1e30f : s_acc[j][0] * scale;
                    s_acc[j][1] = (cg + 1 > rg0)     ? -1e30f : s_acc[j][1] * scale;
                    s_acc[j][2] = (cg     > rg0 + 8) ? -1e30f : s_acc[j][2] * scale;
                    s_acc[j][3] = (cg + 1 > rg0 + 8) ? -1e30f : s_acc[j][3] * scale;
                } else {
                    s_acc[j][0] *= scale; s_acc[j][1] *= scale;
                    s_acc[j][2] *= scale; s_acc[j][3] *= scale;
                }
            }

            // ---- online softmax (row stats within 4-lane quad) ----
            float mx0 = -1e30f, mx1 = -1e30f;
#pragma unroll
            for (int j = 0; j < 8; j++) {
                mx0 = fmaxf(mx0, fmaxf(s_acc[j][0], s_acc[j][1]));
                mx1 = fmaxf(mx1, fmaxf(s_acc[j][2], s_acc[j][3]));
            }
            mx0 = fmaxf(mx0, __shfl_xor_sync(0xffffffffu, mx0, 1));
            mx0 = fmaxf(mx0, __shfl_xor_sync(0xffffffffu, mx0, 2));
            mx1 = fmaxf(mx1, __shfl_xor_sync(0xffffffffu, mx1, 1));
            mx1 = fmaxf(mx1, __shfl_xor_sync(0xffffffffu, mx1, 2));
            float mn0 = fmaxf(m0, mx0), mn1 = fmaxf(m1, mx1);

            float la0 = 0.f, la1 = 0.f;
#pragma unroll
            for (int j = 0; j < 8; j++) {
                float p0 = __expf(s_acc[j][0] - mn0);
                float p1 = __expf(s_acc[j][1] - mn0);
                float p2 = __expf(s_acc[j][2] - mn1);
                float p3 = __expf(s_acc[j][3] - mn1);
                s_acc[j][0] = p0; s_acc[j][1] = p1; s_acc[j][2] = p2; s_acc[j][3] = p3;
                la0 += p0 + p1; la1 += p2 + p3;
            }
            la0 += __shfl_xor_sync(0xffffffffu, la0, 1);
            la0 += __shfl_xor_sync(0xffffffffu, la0, 2);
            la1 += __shfl_xor_sync(0xffffffffu, la1, 1);
            la1 += __shfl_xor_sync(0xffffffffu, la1, 2);

            float f0 = __expf(m0 - mn0), f1 = __expf(m1 - mn1);
            l0 = l0 * f0 + la0; l1 = l1 * f1 + la1;
            m0 = mn0; m1 = mn1;
#pragma unroll
            for (int nt = 0; nt < 16; nt++) {
                o[nt][0] *= f0; o[nt][1] *= f0;
                o[nt][2] *= f1; o[nt][3] *= f1;
            }

            // ---- O += P V (3xBF16, P split in-register) ----
#pragma unroll
            for (int s4 = 0; s4 < 4; s4++) {
                uint32_t pah[4], pal[4];
                {
                    const float* t0 = s_acc[2*s4];
                    const float* t1 = s_acc[2*s4+1];
                    float pv[8] = {t0[0], t0[1], t0[2], t0[3], t1[0], t1[1], t1[2], t1[3]};
#pragma unroll
                    for (int q = 0; q < 4; q++) {
                        __nv_bfloat16 hA = __float2bfloat16(pv[2*q]);
                        __nv_bfloat16 hB = __float2bfloat16(pv[2*q+1]);
                        pah[q] = pack2(hA, hB);
                        pal[q] = pack2(__float2bfloat16(pv[2*q]   - __bfloat162float(hA)),
                                       __float2bfloat16(pv[2*q+1] - __bfloat162float(hB)));
                    }
                }
#pragma unroll
                for (int g = 0; g < 8; g++) {
                    int nrow = g * 16 + (lane & 7) + ((lane >> 4) << 3);
                    int kc   = 2 * s4 + ((lane >> 3) & 1);
                    uint32_t voff = (uint32_t)(nrow * 128 + ((kc ^ (lane & 7)) << 4));
                    uint32_t h0, h1, h2, h3, z0, z1, z2, z3;
                    LDSM_X4(h0, h1, h2, h3, sb + SVH_OFF(st) + voff);
                    LDSM_X4(z0, z1, z2, z3, sb + SVH_OFF(st) + 16384 + voff);
                    uint32_t vh0[2] = {h0, h1}, vh1[2] = {h2, h3};
                    uint32_t vl0[2] = {z0, z1}, vl1[2] = {z2, z3};
                    MMA_BF16(o[2*g],   pah, vh0);
                    MMA_BF16(o[2*g],   pal, vh0);
                    MMA_BF16(o[2*g],   pah, vl0);
                    MMA_BF16(o[2*g+1], pah, vh1);
                    MMA_BF16(o[2*g+1], pal, vh1);
                    MMA_BF16(o[2*g+1], pah, vl1);
                }
            }
        }

        __syncthreads();
        if (kt + 2 < nk) {
            att_issue_kv(sb, st, kt + 2, bh, tid, kh, kl, vh, vl);
            CP_COMMIT();
        }
    }

    // ---- epilogue: normalize, split hi/lo, write ctx [b*2048+s][2048] ----
    const int b_ = bh >> 4, h_ = bh & 15;
    const int srow = qt * 128 + w * 16 + (lane >> 2);
    const float inv0 = 1.f / l0, inv1 = 1.f / l1;
    const size_t base0 = ((size_t)(b_ * Sdim) + srow) * Mdim + h_ * Ddim;
#pragma unroll
    for (int nt = 0; nt < 16; nt++) {
        int col = 8 * nt + 2 * (lane & 3);
        float v0 = o[nt][0] * inv0, v1 = o[nt][1] * inv0;
        float v2 = o[nt][2] * inv1, v3 = o[nt][3] * inv1;
        __nv_bfloat16 h0 = __float2bfloat16(v0), h1v = __float2bfloat16(v1);
        __nv_bfloat16 h2 = __float2bfloat16(v2), h3v = __float2bfloat16(v3);
        *(unsigned*)(ch + base0 + col) = pack2(h0, h1v);
        *(unsigned*)(cl + base0 + col) =
            pack2(__float2bfloat16(v0 - __bfloat162float(h0)),
                  __float2bfloat16(v1 - __bfloat162float(h1v)));
        *(unsigned*)(ch + base0 + 8 * (size_t)Mdim + col) = pack2(h2, h3v);
        *(unsigned*)(cl + base0 + 8 * (size_t)Mdim + col) =
            pack2(__float2bfloat16(v2 - __bfloat162float(h2)),
                  __float2bfloat16(v3 - __bfloat162float(h3v)));
    }
}

// ---------------------------------------------------------------------------
extern "C" void kernel_launch(void* const* d_in, const int* in_sizes, int n_in,
                              void* d_out, int out_size) {
    const float* x    = (const float*)d_in[0];
    const float* Wqkv = (const float*)d_in[1];
    const float* Wo   = (const float*)d_in[2];
    float* out = (float*)d_out;

    float* qkv = nullptr;
    __nv_bfloat16 *xh, *xl, *wqh, *wql, *woh, *wol, *ch, *cl;
    __nv_bfloat16 *qh, *ql, *kh, *kl, *vh, *vl;
    cudaGetSymbolAddress((void**)&qkv, g_qkv);
    cudaGetSymbolAddress((void**)&xh,  g_xh);
    cudaGetSymbolAddress((void**)&xl,  g_xl);
    cudaGetSymbolAddress((void**)&wqh, g_wqh);
    cudaGetSymbolAddress((void**)&wql, g_wql);
    cudaGetSymbolAddress((void**)&woh, g_woh);
    cudaGetSymbolAddress((void**)&wol, g_wol);
    cudaGetSymbolAddress((void**)&ch,  g_ch);
    cudaGetSymbolAddress((void**)&cl,  g_cl);
    cudaGetSymbolAddress((void**)&qh,  g_qh);
    cudaGetSymbolAddress((void**)&ql,  g_ql);
    cudaGetSymbolAddress((void**)&kh,  g_kh);
    cudaGetSymbolAddress((void**)&kl,  g_kl);
    cudaGetSymbolAddress((void**)&vh,  g_vh);
    cudaGetSymbolAddress((void**)&vl,  g_vl);

    cudaFuncSetAttribute(gemm_bf16x3, cudaFuncAttributeMaxDynamicSharedMemorySize,
                         GEMM_SMEM);
    cudaFuncSetAttribute(flash_attn_tc, cudaFuncAttributeMaxDynamicSharedMemorySize,
                         ATT_SMEM);

    // 0) operand prep
    transpose_split<<<dim3(N_QKV / 32, Mdim / 32), dim3(32, 8)>>>(Wqkv, wqh, wql,
                                                                  Mdim, N_QKV);
    transpose_split<<<dim3(Mdim / 32, Mdim / 32), dim3(32, 8)>>>(Wo, woh, wol,
                                                                 Mdim, Mdim);
    split_fp32<<<((size_t)Rrows * Mdim / 4) / 256, 256>>>(x, xh, xl);

    // 1) qkv = x @ Wqkv
    gemm_bf16x3<<<dim3(N_QKV / BN, Rrows / BM), 256, GEMM_SMEM>>>(
        xh, xl, wqh, wql, qkv, N_QKV, Mdim);

    // 2) RoPE + split q,k ; transpose+split v
    rope_split<<<(Rrows * Hdim * (Ddim / 2)) / 256, 256>>>(qkv, qh, ql, kh, kl);
    vsplitT<<<dim3(Sdim / 32, Hdim * 4, Bdim), dim3(32, 8)>>>(qkv, vh, vl);

    // 3) tensor-core causal flash attention -> ctx (bf16 hi/lo)
    flash_attn_tc<<<dim3(Sdim / 128, BH), 256, ATT_SMEM>>>(qh, ql, kh, kl, vh, vl,
                                                           ch, cl);

    // 4) out = ctx @ Wo
    gemm_bf16x3<<<dim3(Mdim / BN, Rrows / BM), 256, GEMM_SMEM>>>(
        ch, cl, woh, wol, out, Mdim, Mdim);
}

// round 5
// speedup vs baseline: 2.9889x; 1.1059x over previous
#include <cuda_runtime.h>
#include <cuda_bf16.h>
#include <cuda_fp16.h>
#include <math.h>
#include <stdint.h>

#define Bdim 4
#define Sdim 2048
#define Mdim 2048
#define Hdim 16
#define Ddim 128
#define Rrows (Bdim * Sdim)          // 8192
#define N_QKV (3 * Hdim * Ddim)      // 6144
#define BH (Bdim * Hdim)             // 64

// Scratch (allocation-free rule: __device__ globals)
__device__ float g_qkv[(size_t)Rrows * N_QKV];                 // ~201 MB
__device__ __half g_x16h[(size_t)Rrows * Mdim];                // x hi (fp16)
__device__ __half g_x16l[(size_t)Rrows * Mdim];                // x lo (fp16)
__device__ __half g_wq16[(size_t)N_QKV * Mdim];                // Wqkv^T (fp16, K-major)
__device__ __nv_bfloat16 g_woh[(size_t)Mdim * Mdim];
__device__ __nv_bfloat16 g_wol[(size_t)Mdim * Mdim];
__device__ __nv_bfloat16 g_ch[(size_t)Rrows * Mdim];
__device__ __nv_bfloat16 g_cl[(size_t)Rrows * Mdim];
// attention operands (bf16 hi/lo)
__device__ __nv_bfloat16 g_qh[(size_t)BH * Sdim * Ddim];       // [bh][s][d]
__device__ __nv_bfloat16 g_ql[(size_t)BH * Sdim * Ddim];
__device__ __nv_bfloat16 g_kh[(size_t)BH * Sdim * Ddim];
__device__ __nv_bfloat16 g_kl[(size_t)BH * Sdim * Ddim];
__device__ __nv_bfloat16 g_vh[(size_t)BH * Ddim * Sdim];       // [bh][d][s]  (V^T)
__device__ __nv_bfloat16 g_vl[(size_t)BH * Ddim * Sdim];

// ============================ helpers ============================
__device__ __forceinline__ uint32_t smem_u32(const void* p) {
    uint32_t a;
    asm("{ .reg .u64 t; cvta.to.shared.u64 t, %1; cvt.u32.u64 %0, t; }"
        : "=r"(a) : "l"(p));
    return a;
}

__device__ __forceinline__ void cp_async16(uint32_t dst, const void* src) {
    asm volatile("cp.async.cg.shared.global [%0], [%1], 16;" :: "r"(dst), "l"(src));
}
#define CP_COMMIT() asm volatile("cp.async.commit_group;" ::: "memory")
#define CP_WAIT0()  asm volatile("cp.async.wait_group 0;" ::: "memory")
#define CP_WAIT1()  asm volatile("cp.async.wait_group 1;" ::: "memory")
#define CP_WAIT2()  asm volatile("cp.async.wait_group 2;" ::: "memory")

#define LDSM_X4(r0, r1, r2, r3, addr)                                        \
    asm volatile("ldmatrix.sync.aligned.m8n8.x4.shared.b16 {%0,%1,%2,%3}, [%4];" \
        : "=r"(r0), "=r"(r1), "=r"(r2), "=r"(r3) : "r"(addr))

#define MMA_BF16(c, a, b)                                                    \
    asm volatile("mma.sync.aligned.m16n8k16.row.col.f32.bf16.bf16.f32 "      \
        "{%0,%1,%2,%3}, {%4,%5,%6,%7}, {%8,%9}, {%0,%1,%2,%3};"              \
        : "+f"((c)[0]), "+f"((c)[1]), "+f"((c)[2]), "+f"((c)[3])             \
        : "r"((a)[0]), "r"((a)[1]), "r"((a)[2]), "r"((a)[3]),                \
          "r"((b)[0]), "r"((b)[1]))

#define MMA_F16(c, a, b)                                                     \
    asm volatile("mma.sync.aligned.m16n8k16.row.col.f32.f16.f16.f32 "        \
        "{%0,%1,%2,%3}, {%4,%5,%6,%7}, {%8,%9}, {%0,%1,%2,%3};"              \
        : "+f"((c)[0]), "+f"((c)[1]), "+f"((c)[2]), "+f"((c)[3])             \
        : "r"((a)[0]), "r"((a)[1]), "r"((a)[2]), "r"((a)[3]),                \
          "r"((b)[0]), "r"((b)[1]))

__device__ __forceinline__ unsigned pack2(__nv_bfloat16 a, __nv_bfloat16 b) {
    return (unsigned)__bfloat16_as_ushort(a) |
           ((unsigned)__bfloat16_as_ushort(b) << 16);
}
__device__ __forceinline__ unsigned pack2h(__half a, __half b) {
    return (unsigned)__half_as_ushort(a) |
           ((unsigned)__half_as_ushort(b) << 16);
}

// ============================ prep kernels ============================
// x fp32 -> fp16 hi/lo
__global__ void split_fp32_f16(const float* __restrict__ in,
                               __half* __restrict__ hi,
                               __half* __restrict__ lo) {
    unsigned i = blockIdx.x * blockDim.x + threadIdx.x;
    float4 v = ((const float4*)in)[i];
    float xs[4] = {v.x, v.y, v.z, v.w};
    __half h[4], l[4];
#pragma unroll
    for (int j = 0; j < 4; j++) {
        h[j] = __float2half_rn(xs[j]);
        l[j] = __float2half_rn(xs[j] - __half2float(h[j]));
    }
    ((uint2*)hi)[i] = make_uint2(pack2h(h[0], h[1]), pack2h(h[2], h[3]));
    ((uint2*)lo)[i] = make_uint2(pack2h(l[0], l[1]), pack2h(l[2], l[3]));
}

// W fp32 [rows x cols] -> W^T fp16 [cols x rows] (single precision term)
__global__ void transpose_f16(const float* __restrict__ in,
                              __half* __restrict__ out,
                              int rows, int cols) {
    __shared__ float t[32][33];
    int x = blockIdx.x * 32 + threadIdx.x;
    int y = blockIdx.y * 32 + threadIdx.y;
#pragma unroll
    for (int j = 0; j < 32; j += 8)
        t[threadIdx.y + j][threadIdx.x] = in[(size_t)(y + j) * cols + x];
    __syncthreads();
    int x2 = blockIdx.y * 32 + threadIdx.x;
    int y2 = blockIdx.x * 32 + threadIdx.y;
#pragma unroll
    for (int j = 0; j < 32; j += 8)
        out[(size_t)(y2 + j) * rows + x2] =
            __float2half_rn(t[threadIdx.x][threadIdx.y + j]);
}

// W fp32 -> W^T bf16 hi/lo
__global__ void transpose_split(const float* __restrict__ in,
                                __nv_bfloat16* __restrict__ hi,
                                __nv_bfloat16* __restrict__ lo,
                                int rows, int cols) {
    __shared__ float t[32][33];
    int x = blockIdx.x * 32 + threadIdx.x;
    int y = blockIdx.y * 32 + threadIdx.y;
#pragma unroll
    for (int j = 0; j < 32; j += 8)
        t[threadIdx.y + j][threadIdx.x] = in[(size_t)(y + j) * cols + x];
    __syncthreads();
    int x2 = blockIdx.y * 32 + threadIdx.x;
    int y2 = blockIdx.x * 32 + threadIdx.y;
#pragma unroll
    for (int j = 0; j < 32; j += 8) {
        float v = t[threadIdx.x][threadIdx.y + j];
        __nv_bfloat16 h = __float2bfloat16(v);
        __nv_bfloat16 l = __float2bfloat16(v - __bfloat162float(h));
        hi[(size_t)(y2 + j) * rows + x2] = h;
        lo[(size_t)(y2 + j) * rows + x2] = l;
    }
}

// ============================ GEMM common tiling ============================
#define BM 128
#define BN 128
#define BK 32
#define TILE_BYTES  (128 * 32 * 2)            // 8192

// ============================ 2xFP16 GEMM (qkv projection) ============================
// C = A @ Bt^T ; A fp16 hi/lo, B fp16 single. 3-stage cp.async pipeline.
#define STAGE_F16   (3 * TILE_BYTES)          // Ah Al Bh = 24576
#define GEMM_SMEM_F16 (3 * STAGE_F16)         // 73728

__device__ __forceinline__ void issue_f16(
    uint32_t sb,
    const __half* __restrict__ Ah, const __half* __restrict__ Al,
    const __half* __restrict__ Bh,
    int m0, int n0, int k0, int K, int tid) {
#pragma unroll
    for (int i = 0; i < 2; i++) {
        int f = i * 256 + tid;
        int r = f >> 2, c = f & 3;
        uint32_t off = (uint32_t)(r * 64 + ((c ^ (r & 3)) << 4));
        size_t ga = (size_t)(m0 + r) * K + k0 + c * 8;
        size_t gb = (size_t)(n0 + r) * K + k0 + c * 8;
        cp_async16(sb + off,                  Ah + ga);
        cp_async16(sb + TILE_BYTES + off,     Al + ga);
        cp_async16(sb + 2 * TILE_BYTES + off, Bh + gb);
    }
}

__global__ __launch_bounds__(256, 2)
void gemm_f16x2(const __half* __restrict__ Ah, const __half* __restrict__ Al,
                const __half* __restrict__ Bh,
                float* __restrict__ C, int Nc, int K) {
    extern __shared__ char smem[];
    const uint32_t sbase = smem_u32(smem);
    const int tid  = threadIdx.x;
    const int wid  = tid >> 5, lane = tid & 31;
    const int wm   = wid & 1,  wn   = wid >> 1;
    const int m0   = blockIdx.y * BM, n0 = blockIdx.x * BN;

    float acc[4][4][4];
#pragma unroll
    for (int a = 0; a < 4; a++)
#pragma unroll
        for (int b = 0; b < 4; b++)
#pragma unroll
            for (int c = 0; c < 4; c++) acc[a][b][c] = 0.f;

    issue_f16(sbase,                 Ah, Al, Bh, m0, n0, 0,      K, tid); CP_COMMIT();
    issue_f16(sbase + STAGE_F16,     Ah, Al, Bh, m0, n0, BK,     K, tid); CP_COMMIT();
    issue_f16(sbase + 2 * STAGE_F16, Ah, Al, Bh, m0, n0, 2 * BK, K, tid); CP_COMMIT();

    const int T = K / BK;
    int st = 0;
    for (int t = 0; t < T; t++) {
        CP_WAIT2();
        __syncthreads();
        const uint32_t sb = sbase + st * STAGE_F16;

#pragma unroll
        for (int s = 0; s < 2; s++) {
            uint32_t bh[4][2];
#pragma unroll
            for (int g = 0; g < 2; g++) {
                int nrow = wn * 32 + g * 16 + (lane & 7) + ((lane >> 4) << 3);
                int kc   = s * 2 + ((lane >> 3) & 1);
                uint32_t addr = sb + 2 * TILE_BYTES +
                                (uint32_t)(nrow * 64 + ((kc ^ (lane & 3)) << 4));
                LDSM_X4(bh[2*g][0], bh[2*g][1], bh[2*g+1][0], bh[2*g+1][1], addr);
            }
            {
                uint32_t ah[4][4];
#pragma unroll
                for (int mt = 0; mt < 4; mt++) {
                    int r  = wm * 64 + mt * 16 + (lane & 15);
                    int kc = s * 2 + (lane >> 4);
                    uint32_t addr = sb +
                        (uint32_t)(r * 64 + ((kc ^ (lane & 3)) << 4));
                    LDSM_X4(ah[mt][0], ah[mt][1], ah[mt][2], ah[mt][3], addr);
                }
#pragma unroll
                for (int mt = 0; mt < 4; mt++)
#pragma unroll
                    for (int nt = 0; nt < 4; nt++)
                        MMA_F16(acc[mt][nt], ah[mt], bh[nt]);
            }
            {
                uint32_t al_[4][4];
#pragma unroll
                for (int mt = 0; mt < 4; mt++) {
                    int r  = wm * 64 + mt * 16 + (lane & 15);
                    int kc = s * 2 + (lane >> 4);
                    uint32_t addr = sb + TILE_BYTES +
                        (uint32_t)(r * 64 + ((kc ^ (lane & 3)) << 4));
                    LDSM_X4(al_[mt][0], al_[mt][1], al_[mt][2], al_[mt][3], addr);
                }
#pragma unroll
                for (int mt = 0; mt < 4; mt++)
#pragma unroll
                    for (int nt = 0; nt < 4; nt++)
                        MMA_F16(acc[mt][nt], al_[mt], bh[nt]);
            }
        }
        __syncthreads();
        if (t + 3 < T)
            issue_f16(sbase + st * STAGE_F16, Ah, Al, Bh, m0, n0, (t + 3) * BK, K, tid);
        CP_COMMIT();
        st = (st == 2) ? 0 : st + 1;
    }

#pragma unroll
    for (int mt = 0; mt < 4; mt++)
#pragma unroll
        for (int nt = 0; nt < 4; nt++) {
            int row = m0 + wm * 64 + mt * 16 + (lane >> 2);
            int col = n0 + wn * 32 + nt * 8 + 2 * (lane & 3);
            *(float2*)(C + (size_t)row * Nc + col) =
                make_float2(acc[mt][nt][0], acc[mt][nt][1]);
            *(float2*)(C + (size_t)(row + 8) * Nc + col) =
                make_float2(acc[mt][nt][2], acc[mt][nt][3]);
        }
}

// ============================ 3xBF16 GEMM (out-proj, 3-stage) ============================
#define STAGE_BF16  (4 * TILE_BYTES)          // Ah Al Bh Bl = 32768
#define GEMM_SMEM_BF16 (3 * STAGE_BF16)       // 98304

__device__ __forceinline__ void issue_bf16(
    uint32_t sb,
    const __nv_bfloat16* __restrict__ Ah, const __nv_bfloat16* __restrict__ Al,
    const __nv_bfloat16* __restrict__ Bh, const __nv_bfloat16* __restrict__ Bl,
    int m0, int n0, int k0, int K, int tid) {
#pragma unroll
    for (int i = 0; i < 2; i++) {
        int f = i * 256 + tid;
        int r = f >> 2, c = f & 3;
        uint32_t off = (uint32_t)(r * 64 + ((c ^ (r & 3)) << 4));
        size_t ga = (size_t)(m0 + r) * K + k0 + c * 8;
        size_t gb = (size_t)(n0 + r) * K + k0 + c * 8;
        cp_async16(sb + off,                  Ah + ga);
        cp_async16(sb + TILE_BYTES + off,     Al + ga);
        cp_async16(sb + 2 * TILE_BYTES + off, Bh + gb);
        cp_async16(sb + 3 * TILE_BYTES + off, Bl + gb);
    }
}

__global__ __launch_bounds__(256, 2)
void gemm_bf16x3(const __nv_bfloat16* __restrict__ Ah,
                 const __nv_bfloat16* __restrict__ Al,
                 const __nv_bfloat16* __restrict__ Bh,
                 const __nv_bfloat16* __restrict__ Bl,
                 float* __restrict__ C, int Nc, int K) {
    extern __shared__ char smem[];
    const uint32_t sbase = smem_u32(smem);
    const int tid  = threadIdx.x;
    const int wid  = tid >> 5, lane = tid & 31;
    const int wm   = wid & 1,  wn   = wid >> 1;
    const int m0   = blockIdx.y * BM, n0 = blockIdx.x * BN;

    float acc[4][4][4];
#pragma unroll
    for (int a = 0; a < 4; a++)
#pragma unroll
        for (int b = 0; b < 4; b++)
#pragma unroll
            for (int c = 0; c < 4; c++) acc[a][b][c] = 0.f;

    issue_bf16(sbase,                  Ah, Al, Bh, Bl, m0, n0, 0,      K, tid); CP_COMMIT();
    issue_bf16(sbase + STAGE_BF16,     Ah, Al, Bh, Bl, m0, n0, BK,     K, tid); CP_COMMIT();
    issue_bf16(sbase + 2 * STAGE_BF16, Ah, Al, Bh, Bl, m0, n0, 2 * BK, K, tid); CP_COMMIT();

    const int T = K / BK;
    int st = 0;
    for (int t = 0; t < T; t++) {
        CP_WAIT2();
        __syncthreads();
        const uint32_t sb = sbase + st * STAGE_BF16;

#pragma unroll
        for (int s = 0; s < 2; s++) {
            uint32_t bh[4][2], bl[4][2];
#pragma unroll
            for (int g = 0; g < 2; g++) {
                int nrow = wn * 32 + g * 16 + (lane & 7) + ((lane >> 4) << 3);
                int kc   = s * 2 + ((lane >> 3) & 1);
                uint32_t addr = sb + 2 * TILE_BYTES +
                                (uint32_t)(nrow * 64 + ((kc ^ (lane & 3)) << 4));
                LDSM_X4(bh[2*g][0], bh[2*g][1], bh[2*g+1][0], bh[2*g+1][1], addr);
                LDSM_X4(bl[2*g][0], bl[2*g][1], bl[2*g+1][0], bl[2*g+1][1],
                        addr + TILE_BYTES);
            }
            {
                uint32_t ah[4][4];
#pragma unroll
                for (int mt = 0; mt < 4; mt++) {
                    int r  = wm * 64 + mt * 16 + (lane & 15);
                    int kc = s * 2 + (lane >> 4);
                    uint32_t addr = sb +
                        (uint32_t)(r * 64 + ((kc ^ (lane & 3)) << 4));
                    LDSM_X4(ah[mt][0], ah[mt][1], ah[mt][2], ah[mt][3], addr);
                }
#pragma unroll
                for (int mt = 0; mt < 4; mt++)
#pragma unroll
                    for (int nt = 0; nt < 4; nt++) {
                        MMA_BF16(acc[mt][nt], ah[mt], bh[nt]);
                        MMA_BF16(acc[mt][nt], ah[mt], bl[nt]);
                    }
            }
            {
                uint32_t al_[4][4];
#pragma unroll
                for (int mt = 0; mt < 4; mt++) {
                    int r  = wm * 64 + mt * 16 + (lane & 15);
                    int kc = s * 2 + (lane >> 4);
                    uint32_t addr = sb + TILE_BYTES +
                        (uint32_t)(r * 64 + ((kc ^ (lane & 3)) << 4));
                    LDSM_X4(al_[mt][0], al_[mt][1], al_[mt][2], al_[mt][3], addr);
                }
#pragma unroll
                for (int mt = 0; mt < 4; mt++)
#pragma unroll
                    for (int nt = 0; nt < 4; nt++)
                        MMA_BF16(acc[mt][nt], al_[mt], bh[nt]);
            }
        }
        __syncthreads();
        if (t + 3 < T)
            issue_bf16(sbase + st * STAGE_BF16, Ah, Al, Bh, Bl,
                       m0, n0, (t + 3) * BK, K, tid);
        CP_COMMIT();
        st = (st == 2) ? 0 : st + 1;
    }

#pragma unroll
    for (int mt = 0; mt < 4; mt++)
#pragma unroll
        for (int nt = 0; nt < 4; nt++) {
            int row = m0 + wm * 64 + mt * 16 + (lane >> 2);
            int col = n0 + wn * 32 + nt * 8 + 2 * (lane & 3);
            *(float2*)(C + (size_t)row * Nc + col) =
                make_float2(acc[mt][nt][0], acc[mt][nt][1]);
            *(float2*)(C + (size_t)(row + 8) * Nc + col) =
                make_float2(acc[mt][nt][2], acc[mt][nt][3]);
        }
}

// ============================ RoPE + split to attention layout ============================
__global__ void rope_split(const float* __restrict__ qkv,
                           __nv_bfloat16* __restrict__ qh, __nv_bfloat16* __restrict__ ql,
                           __nv_bfloat16* __restrict__ kh, __nv_bfloat16* __restrict__ kl) {
    unsigned idx = blockIdx.x * blockDim.x + threadIdx.x;
    int pair = idx & 63;
    int h    = (idx >> 6) & 15;
    unsigned r = idx >> 10;             // 0..8191
    int s = (int)(r & (Sdim - 1));
    int b = (int)(r >> 11);

    double frac  = (double)(2 * pair) / (double)Ddim;
    double theta = (double)s * exp(-frac * 9.210340371976184);
    double sd, cd;
    sincos(theta, &sd, &cd);
    float sn = (float)sd, cs = (float)cd;

    size_t src = (size_t)r * N_QKV + (size_t)h * Ddim + 2 * pair;
    size_t dst = ((size_t)(b * Hdim + h) * Sdim + s) * Ddim + 2 * pair;

    float2 q = *(const float2*)(qkv + src);
    float qx = fmaf(q.x, cs, -q.y * sn);
    float qy = fmaf(q.y, cs,  q.x * sn);
    __nv_bfloat16 hx = __float2bfloat16(qx), hy = __float2bfloat16(qy);
    *(unsigned*)(qh + dst) = pack2(hx, hy);
    *(unsigned*)(ql + dst) = pack2(__float2bfloat16(qx - __bfloat162float(hx)),
                                   __float2bfloat16(qy - __bfloat162float(hy)));

    float2 k = *(const float2*)(qkv + src + 2048);
    float kx = fmaf(k.x, cs, -k.y * sn);
    float ky = fmaf(k.y, cs,  k.x * sn);
    hx = __float2bfloat16(kx); hy = __float2bfloat16(ky);
    *(unsigned*)(kh + dst) = pack2(hx, hy);
    *(unsigned*)(kl + dst) = pack2(__float2bfloat16(kx - __bfloat162float(hx)),
                                   __float2bfloat16(ky - __bfloat162float(hy)));
}

// V -> V^T [bh][d][s] with hi/lo split. grid (S/32, H*4, B), block (32,8)
__global__ void vsplitT(const float* __restrict__ qkv,
                        __nv_bfloat16* __restrict__ vh,
                        __nv_bfloat16* __restrict__ vl) {
    __shared__ float t[32][33];
    int b  = blockIdx.z;
    int h  = blockIdx.y >> 2;
    int d0 = (blockIdx.y & 3) * 32;
    int s0 = blockIdx.x * 32;
#pragma unroll
    for (int j = 0; j < 32; j += 8)
        t[threadIdx.y + j][threadIdx.x] =
            qkv[(size_t)(b * Sdim + s0 + threadIdx.y + j) * N_QKV
                + 4096 + h * Ddim + d0 + threadIdx.x];
    __syncthreads();
#pragma unroll
    for (int j = 0; j < 32; j += 8) {
        float v = t[threadIdx.x][threadIdx.y + j];
        __nv_bfloat16 hh = __float2bfloat16(v);
        size_t o = ((size_t)((b * Hdim + h) * Ddim + d0 + threadIdx.y + j)) * Sdim
                   + s0 + threadIdx.x;
        vh[o] = hh;
        vl[o] = __float2bfloat16(v - __bfloat162float(hh));
    }
}

// ============================ Tensor-core flash attention ============================
#define SQH_OFF 0
#define SQL_OFF 32768
#define SKH_OFF(st) (65536 + (st) * 32768)
#define SVH_OFF(st) (131072 + (st) * 32768)
#define ATT_SMEM 196608

__device__ __forceinline__ void att_issue_kv(
    uint32_t sb, int st, int kt, int bh, int tid,
    const __nv_bfloat16* __restrict__ kh, const __nv_bfloat16* __restrict__ kl,
    const __nv_bfloat16* __restrict__ vh, const __nv_bfloat16* __restrict__ vl) {
    const size_t krow0 = (size_t)bh * Sdim + kt * 64;
    const size_t vrow0 = (size_t)bh * Ddim;
#pragma unroll
    for (int i = 0; i < 4; i++) {           // K: 64 rows x 256B
        int f = i * 256 + tid;
        int r = f >> 4, c = f & 15;
        uint32_t off = (uint32_t)(r * 256 + ((c ^ (r & 7)) << 4));
        const __nv_bfloat16* sh = kh + (krow0 + r) * Ddim + c * 8;
        const __nv_bfloat16* sl = kl + (krow0 + r) * Ddim + c * 8;
        cp_async16(sb + SKH_OFF(st) + off,         sh);
        cp_async16(sb + SKH_OFF(st) + 16384 + off, sl);
    }
#pragma unroll
    for (int i = 0; i < 4; i++) {           // V^T: 128 rows x 128B
        int f = i * 256 + tid;
        int r = f >> 3, c = f & 7;
        uint32_t off = (uint32_t)(r * 128 + ((c ^ (r & 7)) << 4));
        const __nv_bfloat16* sh = vh + (vrow0 + r) * Sdim + kt * 64 + c * 8;
        const __nv_bfloat16* sl = vl + (vrow0 + r) * Sdim + kt * 64 + c * 8;
        cp_async16(sb + SVH_OFF(st) + off,         sh);
        cp_async16(sb + SVH_OFF(st) + 16384 + off, sl);
    }
}

__global__ __launch_bounds__(256, 1)
void flash_attn_tc(const __nv_bfloat16* __restrict__ qh, const __nv_bfloat16* __restrict__ ql,
                   const __nv_bfloat16* __restrict__ kh, const __nv_bfloat16* __restrict__ kl,
                   const __nv_bfloat16* __restrict__ vh, const __nv_bfloat16* __restrict__ vl,
                   __nv_bfloat16* __restrict__ ch, __nv_bfloat16* __restrict__ cl) {
    extern __shared__ char sm[];
    const uint32_t sb = smem_u32(sm);
    const int tid  = threadIdx.x;
    const int w    = tid >> 5, lane = tid & 31;
    const int qt   = (int)(gridDim.x - 1 - blockIdx.x);   // longest first
    const int bh   = blockIdx.y;
    const size_t qrow0 = (size_t)bh * Sdim + qt * 128;

#pragma unroll
    for (int i = 0; i < 8; i++) {
        int f = i * 256 + tid;
        int r = f >> 4, c = f & 15;
        uint32_t off = (uint32_t)(r * 256 + ((c ^ (r & 7)) << 4));
        cp_async16(sb + SQH_OFF + off, qh + (qrow0 + r) * Ddim + c * 8);
        cp_async16(sb + SQL_OFF + off, ql + (qrow0 + r) * Ddim + c * 8);
    }
    CP_COMMIT();

    const int nk = 2 * qt + 2;
    att_issue_kv(sb, 0, 0, bh, tid, kh, kl, vh, vl);
    CP_COMMIT();
    att_issue_kv(sb, 1, 1, bh, tid, kh, kl, vh, vl);
    CP_COMMIT();

    float o[16][4];
#pragma unroll
    for (int nt = 0; nt < 16; nt++)
#pragma unroll
        for (int c = 0; c < 4; c++) o[nt][c] = 0.f;
    float m0 = -1e30f, m1 = -1e30f, l0 = 0.f, l1 = 0.f;

    const float scale = 0.08838834764831845f;
    const int rg0 = qt * 128 + w * 16 + (lane >> 2);

    for (int kt = 0; kt < nk; kt++) {
        if (kt + 1 < nk) CP_WAIT1(); else CP_WAIT0();
        __syncthreads();
        const int st = kt & 1;
        const bool warp_live = (qt * 128 + w * 16 + 15) >= kt * 64;

        if (warp_live) {
            float s_acc[8][4];
#pragma unroll
            for (int j = 0; j < 8; j++)
#pragma unroll
                for (int c = 0; c < 4; c++) s_acc[j][c] = 0.f;

#pragma unroll
            for (int ks = 0; ks < 8; ks++) {
                uint32_t ah[4], al[4];
                {
                    int rA  = w * 16 + (lane & 15);
                    int kcA = 2 * ks + (lane >> 4);
                    uint32_t aoff = (uint32_t)(rA * 256 + ((kcA ^ (lane & 7)) << 4));
                    LDSM_X4(ah[0], ah[1], ah[2], ah[3], sb + SQH_OFF + aoff);
                    LDSM_X4(al[0], al[1], al[2], al[3], sb + SQL_OFF + aoff);
                }
#pragma unroll
                for (int g = 0; g < 4; g++) {
                    int nrow = g * 16 + (lane & 7) + ((lane >> 4) << 3);
                    int kc   = 2 * ks + ((lane >> 3) & 1);
                    uint32_t boff = (uint32_t)(nrow * 256 + ((kc ^ (lane & 7)) << 4));
                    uint32_t h0, h1, h2, h3, z0, z1, z2, z3;
                    LDSM_X4(h0, h1, h2, h3, sb + SKH_OFF(st) + boff);
                    LDSM_X4(z0, z1, z2, z3, sb + SKH_OFF(st) + 16384 + boff);
                    uint32_t bh0[2] = {h0, h1}, bh1[2] = {h2, h3};
                    uint32_t bl0[2] = {z0, z1}, bl1[2] = {z2, z3};
                    MMA_BF16(s_acc[2*g],   ah, bh0);
                    MMA_BF16(s_acc[2*g],   al, bh0);
                    MMA_BF16(s_acc[2*g],   ah, bl0);
                    MMA_BF16(s_acc[2*g+1], ah, bh1);
                    MMA_BF16(s_acc[2*g+1], al, bh1);
                    MMA_BF16(s_acc[2*g+1], ah, bl1);
                }
            }

            const bool tile_masked = (kt * 64 + 63) > (qt * 128 + w * 16);
#pragma unroll
            for (int j = 0; j < 8; j++) {
                int cg = kt * 64 + 8 * j + 2 * (lane & 3);
                if (tile_masked) {
                    s_acc[j][0] = (cg     > rg0)     ? -1e30f : s_acc[j][0] * scale;
                    s_acc[j][1] = (cg + 1 > rg0)     ? -1e30f : s_acc[j][1] * scale;
                    s_acc[j][2] = (cg     > rg0 + 8) ? -1e30f : s_acc[j][2] * scale;
                    s_acc[j][3] = (cg + 1 > rg0 + 8) ? -1e30f : s_acc[j][3] * scale;
                } else {
                    s_acc[j][0] *= scale; s_acc[j][1] *= scale;
                    s_acc[j][2] *= scale; s_acc[j][3] *= scale;
                }
            }

            float mx0 = -1e30f, mx1 = -1e30f;
#pragma unroll
            for (int j = 0; j < 8; j++) {
                mx0 = fmaxf(mx0, fmaxf(s_acc[j][0], s_acc[j][1]));
                mx1 = fmaxf(mx1, fmaxf(s_acc[j][2], s_acc[j][3]));
            }
            mx0 = fmaxf(mx0, __shfl_xor_sync(0xffffffffu, mx0, 1));
            mx0 = fmaxf(mx0, __shfl_xor_sync(0xffffffffu, mx0, 2));
            mx1 = fmaxf(mx1, __shfl_xor_sync(0xffffffffu, mx1, 1));
            mx1 = fmaxf(mx1, __shfl_xor_sync(0xffffffffu, mx1, 2));
            float mn0 = fmaxf(m0, mx0), mn1 = fmaxf(m1, mx1);

            float la0 = 0.f, la1 = 0.f;
#pragma unroll
            for (int j = 0; j < 8; j++) {
                float p0 = __expf(s_acc[j][0] - mn0);
                float p1 = __expf(s_acc[j][1] - mn0);
                float p2 = __expf(s_acc[j][2] - mn1);
                float p3 = __expf(s_acc[j][3] - mn1);
                s_acc[j][0] = p0; s_acc[j][1] = p1; s_acc[j][2] = p2; s_acc[j][3] = p3;
                la0 += p0 + p1; la1 += p2 + p3;
            }
            la0 += __shfl_xor_sync(0xffffffffu, la0, 1);
            la0 += __shfl_xor_sync(0xffffffffu, la0, 2);
            la1 += __shfl_xor_sync(0xffffffffu, la1, 1);
            la1 += __shfl_xor_sync(0xffffffffu, la1, 2);

            float f0 = __expf(m0 - mn0), f1 = __expf(m1 - mn1);
            l0 = l0 * f0 + la0; l1 = l1 * f1 + la1;
            m0 = mn0; m1 = mn1;
#pragma unroll
            for (int nt = 0; nt < 16; nt++) {
                o[nt][0] *= f0; o[nt][1] *= f0;
                o[nt][2] *= f1; o[nt][3] *= f1;
            }

#pragma unroll
            for (int s4 = 0; s4 < 4; s4++) {
                uint32_t pah[4], pal[4];
                {
                    const float* t0 = s_acc[2*s4];
                    const float* t1 = s_acc[2*s4+1];
                    float pv[8] = {t0[0], t0[1], t0[2], t0[3], t1[0], t1[1], t1[2], t1[3]};
#pragma unroll
                    for (int q = 0; q < 4; q++) {
                        __nv_bfloat16 hA = __float2bfloat16(pv[2*q]);
                        __nv_bfloat16 hB = __float2bfloat16(pv[2*q+1]);
                        pah[q] = pack2(hA, hB);
                        pal[q] = pack2(__float2bfloat16(pv[2*q]   - __bfloat162float(hA)),
                                       __float2bfloat16(pv[2*q+1] - __bfloat162float(hB)));
                    }
                }
#pragma unroll
                for (int g = 0; g < 8; g++) {
                    int nrow = g * 16 + (lane & 7) + ((lane >> 4) << 3);
                    int kc   = 2 * s4 + ((lane >> 3) & 1);
                    uint32_t voff = (uint32_t)(nrow * 128 + ((kc ^ (lane & 7)) << 4));
                    uint32_t h0, h1, h2, h3, z0, z1, z2, z3;
                    LDSM_X4(h0, h1, h2, h3, sb + SVH_OFF(st) + voff);
                    LDSM_X4(z0, z1, z2, z3, sb + SVH_OFF(st) + 16384 + voff);
                    uint32_t vh0[2] = {h0, h1}, vh1[2] = {h2, h3};
                    uint32_t vl0[2] = {z0, z1}, vl1[2] = {z2, z3};
                    MMA_BF16(o[2*g],   pah, vh0);
                    MMA_BF16(o[2*g],   pal, vh0);
                    MMA_BF16(o[2*g],   pah, vl0);
                    MMA_BF16(o[2*g+1], pah, vh1);
                    MMA_BF16(o[2*g+1], pal, vh1);
                    MMA_BF16(o[2*g+1], pah, vl1);
                }
            }
        }

        __syncthreads();
        if (kt + 2 < nk) {
            att_issue_kv(sb, st, kt + 2, bh, tid, kh, kl, vh, vl);
            CP_COMMIT();
        }
    }

    const int b_ = bh >> 4, h_ = bh & 15;
    const int srow = qt * 128 + w * 16 + (lane >> 2);
    const float inv0 = 1.f / l0, inv1 = 1.f / l1;
    const size_t base0 = ((size_t)(b_ * Sdim) + srow) * Mdim + h_ * Ddim;
#pragma unroll
    for (int nt = 0; nt < 16; nt++) {
        int col = 8 * nt + 2 * (lane & 3);
        float v0 = o[nt][0] * inv0, v1 = o[nt][1] * inv0;
        float v2 = o[nt][2] * inv1, v3 = o[nt][3] * inv1;
        __nv_bfloat16 h0 = __float2bfloat16(v0), h1v = __float2bfloat16(v1);
        __nv_bfloat16 h2 = __float2bfloat16(v2), h3v = __float2bfloat16(v3);
        *(unsigned*)(ch + base0 + col) = pack2(h0, h1v);
        *(unsigned*)(cl + base0 + col) =
            pack2(__float2bfloat16(v0 - __bfloat162float(h0)),
                  __float2bfloat16(v1 - __bfloat162float(h1v)));
        *(unsigned*)(ch + base0 + 8 * (size_t)Mdim + col) = pack2(h2, h3v);
        *(unsigned*)(cl + base0 + 8 * (size_t)Mdim + col) =
            pack2(__float2bfloat16(v2 - __bfloat162float(h2)),
                  __float2bfloat16(v3 - __bfloat162float(h3v)));
    }
}

// ---------------------------------------------------------------------------
extern "C" void kernel_launch(void* const* d_in, const int* in_sizes, int n_in,
                              void* d_out, int out_size) {
    const float* x    = (const float*)d_in[0];
    const float* Wqkv = (const float*)d_in[1];
    const float* Wo   = (const float*)d_in[2];
    float* out = (float*)d_out;

    float* qkv = nullptr;
    __half *x16h, *x16l, *wq16;
    __nv_bfloat16 *woh, *wol, *ch, *cl;
    __nv_bfloat16 *qh, *ql, *kh, *kl, *vh, *vl;
    cudaGetSymbolAddress((void**)&qkv,  g_qkv);
    cudaGetSymbolAddress((void**)&x16h, g_x16h);
    cudaGetSymbolAddress((void**)&x16l, g_x16l);
    cudaGetSymbolAddress((void**)&wq16, g_wq16);
    cudaGetSymbolAddress((void**)&woh,  g_woh);
    cudaGetSymbolAddress((void**)&wol,  g_wol);
    cudaGetSymbolAddress((void**)&ch,   g_ch);
    cudaGetSymbolAddress((void**)&cl,   g_cl);
    cudaGetSymbolAddress((void**)&qh,   g_qh);
    cudaGetSymbolAddress((void**)&ql,   g_ql);
    cudaGetSymbolAddress((void**)&kh,   g_kh);
    cudaGetSymbolAddress((void**)&kl,   g_kl);
    cudaGetSymbolAddress((void**)&vh,   g_vh);
    cudaGetSymbolAddress((void**)&vl,   g_vl);

    cudaFuncSetAttribute(gemm_f16x2, cudaFuncAttributeMaxDynamicSharedMemorySize,
                         GEMM_SMEM_F16);
    cudaFuncSetAttribute(gemm_bf16x3, cudaFuncAttributeMaxDynamicSharedMemorySize,
                         GEMM_SMEM_BF16);
    cudaFuncSetAttribute(flash_attn_tc, cudaFuncAttributeMaxDynamicSharedMemorySize,
                         ATT_SMEM);

    // 0) operand prep
    transpose_f16<<<dim3(N_QKV / 32, Mdim / 32), dim3(32, 8)>>>(Wqkv, wq16,
                                                                Mdim, N_QKV);
    transpose_split<<<dim3(Mdim / 32, Mdim / 32), dim3(32, 8)>>>(Wo, woh, wol,
                                                                 Mdim, Mdim);
    split_fp32_f16<<<((size_t)Rrows * Mdim / 4) / 256, 256>>>(x, x16h, x16l);

    // 1) qkv = x @ Wqkv  (2xFP16 tensor-core GEMM)
    gemm_f16x2<<<dim3(N_QKV / BN, Rrows / BM), 256, GEMM_SMEM_F16>>>(
        x16h, x16l, wq16, qkv, N_QKV, Mdim);

    // 2) RoPE + split q,k ; transpose+split v
    rope_split<<<(Rrows * Hdim * (Ddim / 2)) / 256, 256>>>(qkv, qh, ql, kh, kl);
    vsplitT<<<dim3(Sdim / 32, Hdim * 4, Bdim), dim3(32, 8)>>>(qkv, vh, vl);

    // 3) tensor-core causal flash attention -> ctx (bf16 hi/lo)
    flash_attn_tc<<<dim3(Sdim / 128, BH), 256, ATT_SMEM>>>(qh, ql, kh, kl, vh, vl,
                                                           ch, cl);

    // 4) out = ctx @ Wo  (3xBF16 tensor-core GEMM, 3-stage)
    gemm_bf16x3<<<dim3(Mdim / BN, Rrows / BM), 256, GEMM_SMEM_BF16>>>(
        ch, cl, woh, wol, out, Mdim, Mdim);
}